// round 4
// baseline (speedup 1.0000x reference)
#include <cuda_runtime.h>
#include <math.h>

#define BB 128
#define TT 256
#define DD 512
#define HH 256
#define NC 96
#define BT (BB*TT)

// ---------------- scratch (static device globals; no runtime alloc) --------
__device__ float g_xg1f[(size_t)BT*1024];
__device__ float g_xg1b[(size_t)BT*1024];
__device__ float g_xg2f[(size_t)BT*1024];
__device__ float g_xg2b[(size_t)BT*1024];
__device__ float g_h1f[(size_t)BT*HH];
__device__ float g_h1b[(size_t)BT*HH];
__device__ float g_hcat[(size_t)BT*2*HH];
__device__ float g_xgFf[(size_t)BT*384];
__device__ float g_xgBf[(size_t)BT*384];
__device__ float g_hstate[2*HH*BB];
__device__ float g_cstate[2*HH*BB];

// ---------------------------------------------------------------------------
// GEMM: C[M,N] = A[M,K] @ B[K,N] + bias[N]   fp32, tile 128x64, BK=16
// ---------------------------------------------------------------------------
__global__ __launch_bounds__(256)
void gemm_bias_kernel(const float* __restrict__ A, const float* __restrict__ Bm,
                      const float* __restrict__ bias, float* __restrict__ C,
                      int M, int N, int K)
{
    __shared__ float As[16][132];   // As[k][m]
    __shared__ float Bs[16][64];

    const int tid  = threadIdx.x;
    const int m0   = blockIdx.y * 128;
    const int n0   = blockIdx.x * 64;
    const int trow = tid >> 4;      // 0..15 -> rows trow*8..+7
    const int tcol = tid & 15;      // 0..15 -> cols tcol*4..+3

    float acc[8][4];
#pragma unroll
    for (int i = 0; i < 8; i++)
#pragma unroll
        for (int j = 0; j < 4; j++) acc[i][j] = 0.0f;

    for (int k0 = 0; k0 < K; k0 += 16) {
#pragma unroll
        for (int i = 0; i < 8; i++) {
            int lin = i * 256 + tid;                 // 2048 = 128 rows x 16 k
            int r = lin >> 4, kk = lin & 15;
            As[kk][r] = A[(size_t)(m0 + r) * K + k0 + kk];
        }
#pragma unroll
        for (int i = 0; i < 4; i++) {
            int lin = i * 256 + tid;                 // 1024 = 16 k x 64 n
            int kk = lin >> 6, c = lin & 63;
            Bs[kk][c] = Bm[(size_t)(k0 + kk) * N + n0 + c];
        }
        __syncthreads();
#pragma unroll
        for (int kk = 0; kk < 16; kk++) {
            float4 a0 = *(const float4*)&As[kk][trow * 8];
            float4 a1 = *(const float4*)&As[kk][trow * 8 + 4];
            float4 b0 = *(const float4*)&Bs[kk][tcol * 4];
            float av[8] = {a0.x, a0.y, a0.z, a0.w, a1.x, a1.y, a1.z, a1.w};
            float bv[4] = {b0.x, b0.y, b0.z, b0.w};
#pragma unroll
            for (int i = 0; i < 8; i++)
#pragma unroll
                for (int j = 0; j < 4; j++) acc[i][j] += av[i] * bv[j];
        }
        __syncthreads();
    }

    float bz[4];
#pragma unroll
    for (int j = 0; j < 4; j++) bz[j] = bias[n0 + tcol * 4 + j];
#pragma unroll
    for (int i = 0; i < 8; i++) {
        size_t row = m0 + trow * 8 + i;
        float4 v;
        v.x = acc[i][0] + bz[0]; v.y = acc[i][1] + bz[1];
        v.z = acc[i][2] + bz[2]; v.w = acc[i][3] + bz[3];
        *(float4*)&C[row * N + n0 + tcol * 4] = v;
    }
}

// ---------------------------------------------------------------------------
// One LSTM time step (H=256, tanh), both directions. Grid (8,8,2):
//   x: unit tile (32 units), y: batch tile (16 samples), z: direction.
// Wh cols handled by a CTA: {g*256 + u0 + 0..31} for g=0..3 (128 cols).
// h/c state layout: [dir][u][b] (u-major) so hT loads are coalesced.
// ---------------------------------------------------------------------------
#define SCAN_SMEM ((256*128 + 256*16 + 128*17) * 4)

__global__ __launch_bounds__(256)
void scan_step_kernel(const float* __restrict__ xgF, const float* __restrict__ xgB,
                      const float* __restrict__ WhF, const float* __restrict__ WhB,
                      float* __restrict__ outF, float* __restrict__ outB,
                      int outStride, int offF, int offB, int s)
{
    extern __shared__ float sm[];
    float* Ws = sm;                 // [256 k][128 c]
    float* hT = Ws + 256 * 128;     // [256 k][16 b]
    float* zS = hT + 256 * 16;      // [128 c][17]

    const int tid = threadIdx.x;
    const int u0  = blockIdx.x * 32;
    const int b0  = blockIdx.y * 16;
    const int dir = blockIdx.z;
    const float* Wh = dir ? WhB : WhF;
    const float* xg = dir ? xgB : xgF;
    float* out = dir ? outB : outF;
    const int off = dir ? offB : offF;
    float* hst = g_hstate + dir * (HH * BB);
    float* cst = g_cstate + dir * (HH * BB);
    const int t = dir ? (TT - 1 - s) : s;

    // stage Wh slice: Ws[k][g*32+q] = Wh[k][g*256+u0+q]
#pragma unroll
    for (int i = 0; i < 32; i++) {
        int v = i * 256 + tid;              // float4 index, 8192 total
        int k = v >> 5, c4 = v & 31;
        int gate = c4 >> 3, q = c4 & 7;
        float4 w = *(const float4*)(Wh + (size_t)k * 1024 + gate * 256 + u0 + q * 4);
        *(float4*)(Ws + k * 128 + gate * 32 + q * 4) = w;
    }
    // stage h transposed: hT[k][b]
#pragma unroll
    for (int i = 0; i < 4; i++) {
        int v = i * 256 + tid;              // float4 index, 1024 total
        int k = v >> 2, b4 = v & 3;
        float4 h = *(const float4*)(hst + k * 128 + b0 + b4 * 4);
        *(float4*)(hT + k * 16 + b4 * 4) = h;
    }
    __syncthreads();

    // z = h @ Wh : thread = 4b x 2c
    const int tx = tid & 63;
    const int ty = tid >> 6;
    float a00=0,a01=0,a10=0,a11=0,a20=0,a21=0,a30=0,a31=0;
    const float* hp = hT + ty * 4;
    const float* wp = Ws + tx * 2;
#pragma unroll 4
    for (int k = 0; k < 256; k++) {
        float4 h4 = *(const float4*)(hp + k * 16);
        float2 w2 = *(const float2*)(wp + k * 128);
        a00 += h4.x * w2.x; a01 += h4.x * w2.y;
        a10 += h4.y * w2.x; a11 += h4.y * w2.y;
        a20 += h4.z * w2.x; a21 += h4.z * w2.y;
        a30 += h4.w * w2.x; a31 += h4.w * w2.y;
    }
    {
        int c0 = tx * 2, r = ty * 4;
        zS[c0 * 17 + r + 0] = a00; zS[(c0 + 1) * 17 + r + 0] = a01;
        zS[c0 * 17 + r + 1] = a10; zS[(c0 + 1) * 17 + r + 1] = a11;
        zS[c0 * 17 + r + 2] = a20; zS[(c0 + 1) * 17 + r + 2] = a21;
        zS[c0 * 17 + r + 3] = a30; zS[(c0 + 1) * 17 + r + 3] = a31;
    }
    __syncthreads();

    // gates: thread -> (b = tid>>4, u = u0 + (tid&15) + 16*i)
    const int b  = tid >> 4;
    const int uu = tid & 15;
    const int bg = b0 + b;
#pragma unroll
    for (int i = 0; i < 2; i++) {
        int ul = uu + 16 * i;
        int u  = u0 + ul;
        size_t row = ((size_t)bg * TT + t) * 1024;
        float zi = zS[(0 * 32 + ul) * 17 + b] + xg[row + 0 * 256 + u];
        float zf = zS[(1 * 32 + ul) * 17 + b] + xg[row + 1 * 256 + u];
        float zg = zS[(2 * 32 + ul) * 17 + b] + xg[row + 2 * 256 + u];
        float zo = zS[(3 * 32 + ul) * 17 + b] + xg[row + 3 * 256 + u];
        float iv = 1.f / (1.f + expf(-zi));
        float fv = 1.f / (1.f + expf(-zf));
        float ov = 1.f / (1.f + expf(-zo));
        float cold = cst[u * BB + bg];
        float cn = fv * cold + iv * tanhf(zg);
        float hn = ov * tanhf(cn);
        cst[u * BB + bg] = cn;
        hst[u * BB + bg] = hn;
        out[((size_t)bg * TT + t) * outStride + off + u] = hn;
    }
}

// ---------------------------------------------------------------------------
// Final LSTMs (C=96, softmax activation), one CTA per sample, fwd then bwd.
// ---------------------------------------------------------------------------
__device__ __forceinline__ float blockReduce96(float v, bool isMax,
                                               volatile float* red, int tid)
{
#pragma unroll
    for (int o = 16; o > 0; o >>= 1) {
        float w = __shfl_down_sync(0xffffffffu, v, o);
        v = isMax ? fmaxf(v, w) : v + w;
    }
    if (tid < 96 && (tid & 31) == 0) red[tid >> 5] = v;
    __syncthreads();
    float r = isMax ? fmaxf(fmaxf(red[0], red[1]), red[2])
                    : red[0] + red[1] + red[2];
    __syncthreads();
    return r;
}

#define FIN_SMEM ((96*384 + 384 + 96 + 96 + 4) * 4)

__global__ __launch_bounds__(384)
void final_lstm_kernel(const float* __restrict__ xgF, const float* __restrict__ xgB,
                       const float* __restrict__ WhF, const float* __restrict__ WhB,
                       float* __restrict__ pot)
{
    extern __shared__ float sm[];
    float* WhS = sm;              // [96][384]
    float* zS  = WhS + 96 * 384;  // [384]
    float* hS  = zS + 384;        // [96]
    float* cS  = hS + 96;         // [96]
    float* red = cS + 96;         // [4]
    const int tid = threadIdx.x;
    const int b = blockIdx.x;

    for (int dir = 0; dir < 2; dir++) {
        const float* Wh = dir ? WhB : WhF;
        const float* xg = dir ? xgB : xgF;
        for (int i = tid; i < 96 * 384; i += 384) WhS[i] = Wh[i];
        if (tid < 96) { hS[tid] = 0.f; cS[tid] = 0.f; }
        __syncthreads();

        for (int s = 0; s < TT; s++) {
            int t = dir ? (TT - 1 - s) : s;
            float a = xg[((size_t)b * TT + t) * 384 + tid];
#pragma unroll 4
            for (int k = 0; k < 96; k++) a += hS[k] * WhS[k * 384 + tid];
            zS[tid] = a;
            __syncthreads();

            bool v = tid < 96;
            float gv = v ? zS[192 + tid] : -1e30f;
            float gmax = blockReduce96(gv, true, red, tid);
            float ge = v ? expf(gv - gmax) : 0.f;
            float gsum = blockReduce96(ge, false, red, tid);
            float cn = 0.f;
            if (v) {
                float iv = 1.f / (1.f + expf(-zS[tid]));
                float fv = 1.f / (1.f + expf(-zS[96 + tid]));
                cn = fv * cS[tid] + iv * (ge / gsum);
            }
            float cmax = blockReduce96(v ? cn : -1e30f, true, red, tid);
            float ce = v ? expf(cn - cmax) : 0.f;
            float csum = blockReduce96(ce, false, red, tid);
            if (v) {
                float ov = 1.f / (1.f + expf(-zS[288 + tid]));
                float hv = ov * (ce / csum);
                cS[tid] = cn;
                hS[tid] = hv;
                size_t pi = ((size_t)b * TT + t) * 96 + tid;
                if (dir == 0) pot[pi] = hv; else pot[pi] += hv;
            }
            __syncthreads();
        }
        __syncthreads();
    }
}

// ---------------------------------------------------------------------------
// Viterbi: one CTA per sample; first-max tie-breaking matches jnp.argmax.
// ---------------------------------------------------------------------------
#define VIT_SMEM (96*96*4 + 2*96*4 + 255*96 + 64)

__global__ __launch_bounds__(128)
void viterbi_kernel(const float* __restrict__ pot, const float* __restrict__ trans,
                    float* __restrict__ dec)
{
    extern __shared__ float sm[];
    float* tS  = sm;               // [96][96]
    float* al  = tS + 96 * 96;     // [96]
    float* al2 = al + 96;          // [96]
    unsigned char* bp = (unsigned char*)(al2 + 96);  // [255][96]
    const int tid = threadIdx.x;
    const int b = blockIdx.x;

    for (int i = tid; i < 96 * 96; i += 128) tS[i] = trans[i];
    if (tid < 96) al[tid] = pot[((size_t)b * TT) * 96 + tid];
    __syncthreads();

    for (int t = 1; t < TT; t++) {
        if (tid < 96) {
            float best = -1e30f; int bi = 0;
#pragma unroll 4
            for (int i = 0; i < 96; i++) {
                float sc = al[i] + tS[i * 96 + tid];
                if (sc > best) { best = sc; bi = i; }
            }
            al2[tid] = best + pot[((size_t)b * TT + t) * 96 + tid];
            bp[(t - 1) * 96 + tid] = (unsigned char)bi;
        }
        __syncthreads();
        if (tid < 96) al[tid] = al2[tid];
        __syncthreads();
    }
    if (tid == 0) {
        int bestj = 0; float bv = al[0];
        for (int j = 1; j < 96; j++) if (al[j] > bv) { bv = al[j]; bestj = j; }
        int tag = bestj;
        dec[(size_t)b * TT + TT - 1] = (float)tag;
        for (int t = TT - 2; t >= 0; t--) {
            tag = bp[t * 96 + tag];
            dec[(size_t)b * TT + t] = (float)tag;
        }
    }
}

// ---------------------------------------------------------------------------
extern "C" void kernel_launch(void* const* d_in, const int* in_sizes, int n_in,
                              void* d_out, int out_size)
{
    const float* x    = (const float*)d_in[0];
    const float* Wi1f = (const float*)d_in[1];
    const float* Wh1f = (const float*)d_in[2];
    const float* b1f  = (const float*)d_in[3];
    const float* Wi2f = (const float*)d_in[4];
    const float* Wh2f = (const float*)d_in[5];
    const float* b2f  = (const float*)d_in[6];
    const float* Wi1b = (const float*)d_in[7];
    const float* Wh1b = (const float*)d_in[8];
    const float* b1b  = (const float*)d_in[9];
    const float* Wi2b = (const float*)d_in[10];
    const float* Wh2b = (const float*)d_in[11];
    const float* b2b  = (const float*)d_in[12];
    const float* Wif  = (const float*)d_in[13];
    const float* Whf  = (const float*)d_in[14];
    const float* bf   = (const float*)d_in[15];
    const float* Wib  = (const float*)d_in[16];
    const float* Whb  = (const float*)d_in[17];
    const float* bb   = (const float*)d_in[18];
    const float* trans= (const float*)d_in[19];

    float* dec = (float*)d_out;           // decoded as float, B*T
    float* pot = (float*)d_out + BT;      // potentials, B*T*C

    float *xg1f, *xg1b, *xg2f, *xg2b, *h1f, *h1b, *hcat, *xgFf, *xgBf, *hst, *cst;
    cudaGetSymbolAddress((void**)&xg1f, g_xg1f);
    cudaGetSymbolAddress((void**)&xg1b, g_xg1b);
    cudaGetSymbolAddress((void**)&xg2f, g_xg2f);
    cudaGetSymbolAddress((void**)&xg2b, g_xg2b);
    cudaGetSymbolAddress((void**)&h1f,  g_h1f);
    cudaGetSymbolAddress((void**)&h1b,  g_h1b);
    cudaGetSymbolAddress((void**)&hcat, g_hcat);
    cudaGetSymbolAddress((void**)&xgFf, g_xgFf);
    cudaGetSymbolAddress((void**)&xgBf, g_xgBf);
    cudaGetSymbolAddress((void**)&hst,  g_hstate);
    cudaGetSymbolAddress((void**)&cst,  g_cstate);

    cudaFuncSetAttribute(scan_step_kernel,
                         cudaFuncAttributeMaxDynamicSharedMemorySize, SCAN_SMEM);
    cudaFuncSetAttribute(final_lstm_kernel,
                         cudaFuncAttributeMaxDynamicSharedMemorySize, FIN_SMEM);
    cudaFuncSetAttribute(viterbi_kernel,
                         cudaFuncAttributeMaxDynamicSharedMemorySize, VIT_SMEM);

    dim3 g1(1024 / 64, BT / 128);   // (16, 256)
    gemm_bias_kernel<<<g1, 256>>>(x, Wi1f, b1f, xg1f, BT, 1024, 512);
    gemm_bias_kernel<<<g1, 256>>>(x, Wi1b, b1b, xg1b, BT, 1024, 512);

    cudaMemsetAsync(hst, 0, sizeof(float) * 2 * HH * BB);
    cudaMemsetAsync(cst, 0, sizeof(float) * 2 * HH * BB);
    dim3 gs(8, 8, 2);
    for (int s = 0; s < TT; s++)
        scan_step_kernel<<<gs, 256, SCAN_SMEM>>>(xg1f, xg1b, Wh1f, Wh1b,
                                                 h1f, h1b, 256, 0, 0, s);

    gemm_bias_kernel<<<g1, 256>>>(h1f, Wi2f, b2f, xg2f, BT, 1024, 256);
    gemm_bias_kernel<<<g1, 256>>>(h1b, Wi2b, b2b, xg2b, BT, 1024, 256);

    cudaMemsetAsync(hst, 0, sizeof(float) * 2 * HH * BB);
    cudaMemsetAsync(cst, 0, sizeof(float) * 2 * HH * BB);
    for (int s = 0; s < TT; s++)
        scan_step_kernel<<<gs, 256, SCAN_SMEM>>>(xg2f, xg2b, Wh2f, Wh2b,
                                                 hcat, hcat, 512, 0, 256, s);

    dim3 g2(384 / 64, BT / 128);    // (6, 256)
    gemm_bias_kernel<<<g2, 256>>>(hcat, Wif, bf, xgFf, BT, 384, 512);
    gemm_bias_kernel<<<g2, 256>>>(hcat, Wib, bb, xgBf, BT, 384, 512);

    final_lstm_kernel<<<BB, 384, FIN_SMEM>>>(xgFf, xgBf, Whf, Whb, pot);
    viterbi_kernel<<<BB, 128, VIT_SMEM>>>(pot, trans, dec);
}

// round 5
// speedup vs baseline: 1.3070x; 1.3070x over previous
#include <cuda_runtime.h>
#include <math.h>

#define BB 128
#define TT 256
#define DD 512
#define HH 256
#define NC 96
#define BT (BB*TT)

// ---------------- scratch (static device globals; no runtime alloc) --------
__device__ float g_xg1f[(size_t)BT*1024];
__device__ float g_xg1b[(size_t)BT*1024];
__device__ float g_xg2f[(size_t)BT*1024];
__device__ float g_xg2b[(size_t)BT*1024];
__device__ float g_h1f[(size_t)BT*HH];
__device__ float g_h1b[(size_t)BT*HH];
__device__ float g_hcat[(size_t)BT*2*HH];
__device__ float g_xgFf[(size_t)BT*384];
__device__ float g_xgBf[(size_t)BT*384];
__device__ float g_potB[(size_t)BT*NC];
__device__ float g_hstate[2*2*HH*BB];     // [buf][dir][u][b]
__device__ unsigned g_bar;

// ---------------------------------------------------------------------------
// GEMM: C[M,N] = A[M,K] @ B[K,N] + bias[N]   fp32, tile 128x64, BK=16,
// inner loop uses packed fma.rn.f32x2 (row pairs), bit-identical to scalar FMA.
// ---------------------------------------------------------------------------
__global__ __launch_bounds__(256)
void gemm_bias_kernel(const float* __restrict__ A, const float* __restrict__ Bm,
                      const float* __restrict__ bias, float* __restrict__ C,
                      int M, int N, int K)
{
    __shared__ float As[16][132];   // As[k][m]
    __shared__ float Bs[16][64];

    const int tid  = threadIdx.x;
    const int m0   = blockIdx.y * 128;
    const int n0   = blockIdx.x * 64;
    const int trow = tid >> 4;      // 0..15 -> rows trow*8..+7
    const int tcol = tid & 15;      // 0..15 -> cols tcol*4..+3

    unsigned long long acc[4][4];   // [row-pair p -> rows 2p,2p+1][col j]
#pragma unroll
    for (int p = 0; p < 4; p++)
#pragma unroll
        for (int j = 0; j < 4; j++) acc[p][j] = 0ull;

    for (int k0 = 0; k0 < K; k0 += 16) {
#pragma unroll
        for (int i = 0; i < 8; i++) {
            int lin = i * 256 + tid;                 // 2048 = 128 rows x 16 k
            int r = lin >> 4, kk = lin & 15;
            As[kk][r] = A[(size_t)(m0 + r) * K + k0 + kk];
        }
#pragma unroll
        for (int i = 0; i < 4; i++) {
            int lin = i * 256 + tid;                 // 1024 = 16 k x 64 n
            int kk = lin >> 6, c = lin & 63;
            Bs[kk][c] = Bm[(size_t)(k0 + kk) * N + n0 + c];
        }
        __syncthreads();
#pragma unroll
        for (int kk = 0; kk < 16; kk++) {
            ulonglong2 aP0 = *(const ulonglong2*)&As[kk][trow * 8];      // (r0,r1),(r2,r3)
            ulonglong2 aP1 = *(const ulonglong2*)&As[kk][trow * 8 + 4];  // (r4,r5),(r6,r7)
            float4 b0 = *(const float4*)&Bs[kk][tcol * 4];
            unsigned long long bd0, bd1, bd2, bd3;
            asm("mov.b64 %0, {%1, %1};" : "=l"(bd0) : "f"(b0.x));
            asm("mov.b64 %0, {%1, %1};" : "=l"(bd1) : "f"(b0.y));
            asm("mov.b64 %0, {%1, %1};" : "=l"(bd2) : "f"(b0.z));
            asm("mov.b64 %0, {%1, %1};" : "=l"(bd3) : "f"(b0.w));
            unsigned long long ap[4] = {aP0.x, aP0.y, aP1.x, aP1.y};
            unsigned long long bd[4] = {bd0, bd1, bd2, bd3};
#pragma unroll
            for (int p = 0; p < 4; p++)
#pragma unroll
                for (int j = 0; j < 4; j++)
                    asm("fma.rn.f32x2 %0, %1, %2, %0;"
                        : "+l"(acc[p][j]) : "l"(ap[p]), "l"(bd[j]));
        }
        __syncthreads();
    }

    float bz[4];
#pragma unroll
    for (int j = 0; j < 4; j++) bz[j] = bias[n0 + tcol * 4 + j];
#pragma unroll
    for (int p = 0; p < 4; p++) {
        float lo[4], hi[4];
#pragma unroll
        for (int j = 0; j < 4; j++)
            asm("mov.b64 {%0, %1}, %2;" : "=f"(lo[j]), "=f"(hi[j]) : "l"(acc[p][j]));
        size_t r0 = m0 + trow * 8 + 2 * p;
        float4 v0, v1;
        v0.x = lo[0] + bz[0]; v0.y = lo[1] + bz[1]; v0.z = lo[2] + bz[2]; v0.w = lo[3] + bz[3];
        v1.x = hi[0] + bz[0]; v1.y = hi[1] + bz[1]; v1.z = hi[2] + bz[2]; v1.w = hi[3] + bz[3];
        *(float4*)&C[r0 * N + n0 + tcol * 4] = v0;
        *(float4*)&C[(r0 + 1) * N + n0 + tcol * 4] = v1;
    }
}

// ---------------------------------------------------------------------------
__global__ void reset_bar_kernel() { g_bar = 0u; }

// ---------------------------------------------------------------------------
// Persistent dual-direction LSTM scan (H=256, tanh). Grid (8,8,2) = 128 CTAs,
// 1 CTA/SM (152.5KB smem) -> all co-resident -> software grid barrier is safe.
// Wh slice staged in smem ONCE; h state double-buffered in global via stcg/ldcg;
// cell state in registers. One grid barrier per step.
// ---------------------------------------------------------------------------
#define SCAN_SMEM ((256*128 + 256*16 + 128*17) * 4)

__global__ __launch_bounds__(256, 1)
void scan_persist_kernel(const float* __restrict__ xgF, const float* __restrict__ xgB,
                         const float* __restrict__ WhF, const float* __restrict__ WhB,
                         float* __restrict__ outF, float* __restrict__ outB,
                         int outStride, int offF, int offB)
{
    extern __shared__ float sm[];
    float* Ws = sm;                 // [256 k][128 c]
    float* hT = Ws + 256 * 128;     // [256 k][16 b]
    float* zS = hT + 256 * 16;      // [128 c][17]

    const int tid = threadIdx.x;
    const int u0  = blockIdx.x * 32;
    const int b0  = blockIdx.y * 16;
    const int dir = blockIdx.z;
    const float* Wh = dir ? WhB : WhF;
    const float* xg = dir ? xgB : xgF;
    float* out = dir ? outB : outF;
    const int off = dir ? offB : offF;

    // stage Wh slice once: Ws[k][g*32+q] = Wh[k][g*256+u0+q]
#pragma unroll
    for (int i = 0; i < 32; i++) {
        int v = i * 256 + tid;              // float4 index, 8192 total
        int k = v >> 5, c4 = v & 31;
        int gate = c4 >> 3, q = c4 & 7;
        float4 w = *(const float4*)(Wh + (size_t)k * 1024 + gate * 256 + u0 + q * 4);
        *(float4*)(Ws + k * 128 + gate * 32 + q * 4) = w;
    }

    const int tx = tid & 63;            // c pair index (2 cols)
    const int ty = tid >> 6;            // b quad index (4 rows)
    const float* hp = hT + ty * 4;
    const float* wp = Ws + tx * 2;
    const int gb = tid >> 4;            // gate-phase batch 0..15
    const int gu = tid & 15;            // gate-phase unit 0..15
    const int bg = b0 + gb;
    float creg0 = 0.0f, creg1 = 0.0f;

#pragma unroll 1
    for (int s = 0; s < TT; s++) {
        const int t = dir ? (TT - 1 - s) : s;
        const float* hr = g_hstate + (size_t)(s & 1) * (2 * HH * BB) + dir * (HH * BB);
        float*       hw = g_hstate + (size_t)((s + 1) & 1) * (2 * HH * BB) + dir * (HH * BB);

        // prefetch this thread's xg gate inputs (hides DRAM latency under z compute)
        const size_t xrow = ((size_t)bg * TT + t) * 1024;
        float xv[8];
#pragma unroll
        for (int i = 0; i < 2; i++) {
            int u = u0 + gu + 16 * i;
            xv[i * 4 + 0] = xg[xrow + 0 * 256 + u];
            xv[i * 4 + 1] = xg[xrow + 1 * 256 + u];
            xv[i * 4 + 2] = xg[xrow + 2 * 256 + u];
            xv[i * 4 + 3] = xg[xrow + 3 * 256 + u];
        }

        // stage h (previous step, other CTAs' writes) via L2
#pragma unroll
        for (int i = 0; i < 4; i++) {
            int v = i * 256 + tid;
            int k = v >> 2, b4 = v & 3;
            float4 h = __ldcg((const float4*)(hr + k * 128 + b0 + b4 * 4));
            *(float4*)(hT + k * 16 + b4 * 4) = h;
        }
        __syncthreads();

        // z = h @ Wh, packed f32x2 over b pairs
        unsigned long long pA = 0ull, pB = 0ull, pC = 0ull, pD = 0ull;
#pragma unroll 4
        for (int k = 0; k < 256; k++) {
            ulonglong2 hv = *(const ulonglong2*)(hp + k * 16);   // (b0,b1),(b2,b3)
            float2 w2 = *(const float2*)(wp + k * 128);
            unsigned long long wxx, wyy;
            asm("mov.b64 %0, {%1, %1};" : "=l"(wxx) : "f"(w2.x));
            asm("mov.b64 %0, {%1, %1};" : "=l"(wyy) : "f"(w2.y));
            asm("fma.rn.f32x2 %0, %1, %2, %0;" : "+l"(pA) : "l"(hv.x), "l"(wxx));
            asm("fma.rn.f32x2 %0, %1, %2, %0;" : "+l"(pB) : "l"(hv.y), "l"(wxx));
            asm("fma.rn.f32x2 %0, %1, %2, %0;" : "+l"(pC) : "l"(hv.x), "l"(wyy));
            asm("fma.rn.f32x2 %0, %1, %2, %0;" : "+l"(pD) : "l"(hv.y), "l"(wyy));
        }
        {
            float a00, a10, a20, a30, a01, a11, a21, a31;
            asm("mov.b64 {%0, %1}, %2;" : "=f"(a00), "=f"(a10) : "l"(pA));
            asm("mov.b64 {%0, %1}, %2;" : "=f"(a20), "=f"(a30) : "l"(pB));
            asm("mov.b64 {%0, %1}, %2;" : "=f"(a01), "=f"(a11) : "l"(pC));
            asm("mov.b64 {%0, %1}, %2;" : "=f"(a21), "=f"(a31) : "l"(pD));
            int c0 = tx * 2, r = ty * 4;
            zS[c0 * 17 + r + 0] = a00; zS[(c0 + 1) * 17 + r + 0] = a01;
            zS[c0 * 17 + r + 1] = a10; zS[(c0 + 1) * 17 + r + 1] = a11;
            zS[c0 * 17 + r + 2] = a20; zS[(c0 + 1) * 17 + r + 2] = a21;
            zS[c0 * 17 + r + 3] = a30; zS[(c0 + 1) * 17 + r + 3] = a31;
        }
        __syncthreads();

        // gates
#pragma unroll
        for (int i = 0; i < 2; i++) {
            int ul = gu + 16 * i;
            int u  = u0 + ul;
            float zi = zS[(0 * 32 + ul) * 17 + gb] + xv[i * 4 + 0];
            float zf = zS[(1 * 32 + ul) * 17 + gb] + xv[i * 4 + 1];
            float zg = zS[(2 * 32 + ul) * 17 + gb] + xv[i * 4 + 2];
            float zo = zS[(3 * 32 + ul) * 17 + gb] + xv[i * 4 + 3];
            float iv = 1.f / (1.f + expf(-zi));
            float fv = 1.f / (1.f + expf(-zf));
            float ov = 1.f / (1.f + expf(-zo));
            float cold = i ? creg1 : creg0;
            float cn = fv * cold + iv * tanhf(zg);
            float hn = ov * tanhf(cn);
            if (i) creg1 = cn; else creg0 = cn;
            __stcg(hw + (size_t)u * BB + bg, hn);
            out[((size_t)bg * TT + t) * outStride + off + u] = hn;
        }

        // grid barrier (release h writes, then arrive + spin)
        __syncthreads();
        if (tid == 0) {
            __threadfence();
            atomicAdd(&g_bar, 1u);
            unsigned target = (unsigned)(s + 1) * 128u;
            while (atomicAdd(&g_bar, 0u) < target) { }
        }
        __syncthreads();
    }
}

// ---------------------------------------------------------------------------
// Final LSTMs (C=96, softmax activation), one CTA per (sample, direction).
// dir 0 writes pot (d_out area), dir 1 writes g_potB; Viterbi fuses the sum.
// ---------------------------------------------------------------------------
__device__ __forceinline__ float blockReduce96(float v, bool isMax,
                                               volatile float* red, int tid)
{
#pragma unroll
    for (int o = 16; o > 0; o >>= 1) {
        float w = __shfl_down_sync(0xffffffffu, v, o);
        v = isMax ? fmaxf(v, w) : v + w;
    }
    if (tid < 96 && (tid & 31) == 0) red[tid >> 5] = v;
    __syncthreads();
    float r = isMax ? fmaxf(fmaxf(red[0], red[1]), red[2])
                    : red[0] + red[1] + red[2];
    __syncthreads();
    return r;
}

#define FIN_SMEM ((96*384 + 384 + 96 + 96 + 4) * 4)

__global__ __launch_bounds__(384)
void final_lstm_kernel(const float* __restrict__ xgF, const float* __restrict__ xgB,
                       const float* __restrict__ WhF, const float* __restrict__ WhB,
                       float* __restrict__ potF, float* __restrict__ potB)
{
    extern __shared__ float sm[];
    float* WhS = sm;              // [96][384]
    float* zS  = WhS + 96 * 384;  // [384]
    float* hS  = zS + 384;        // [96]
    float* cS  = hS + 96;         // [96]
    float* red = cS + 96;         // [4]
    const int tid = threadIdx.x;
    const int b = blockIdx.x;
    const int dir = blockIdx.y;

    const float* Wh = dir ? WhB : WhF;
    const float* xg = dir ? xgB : xgF;
    float* pot = dir ? potB : potF;

    for (int i = tid; i < 96 * 384; i += 384) WhS[i] = Wh[i];
    if (tid < 96) { hS[tid] = 0.f; cS[tid] = 0.f; }
    __syncthreads();

    for (int s = 0; s < TT; s++) {
        int t = dir ? (TT - 1 - s) : s;
        float a = xg[((size_t)b * TT + t) * 384 + tid];
#pragma unroll 4
        for (int k = 0; k < 96; k++) a += hS[k] * WhS[k * 384 + tid];
        zS[tid] = a;
        __syncthreads();

        bool v = tid < 96;
        float gv = v ? zS[192 + tid] : -1e30f;
        float gmax = blockReduce96(gv, true, red, tid);
        float ge = v ? expf(gv - gmax) : 0.f;
        float gsum = blockReduce96(ge, false, red, tid);
        float cn = 0.f;
        if (v) {
            float iv = 1.f / (1.f + expf(-zS[tid]));
            float fv = 1.f / (1.f + expf(-zS[96 + tid]));
            cn = fv * cS[tid] + iv * (ge / gsum);
        }
        float cmax = blockReduce96(v ? cn : -1e30f, true, red, tid);
        float ce = v ? expf(cn - cmax) : 0.f;
        float csum = blockReduce96(ce, false, red, tid);
        if (v) {
            float ov = 1.f / (1.f + expf(-zS[288 + tid]));
            float hv = ov * (ce / csum);
            cS[tid] = cn;
            hS[tid] = hv;
            pot[((size_t)b * TT + t) * 96 + tid] = hv;
        }
        __syncthreads();
    }
}

// ---------------------------------------------------------------------------
// Viterbi: one CTA per sample. Fuses pot = pf + pb (writes summed pot to d_out).
// Strict-> comparisons = jnp.argmax first-max tie-breaking.
// ---------------------------------------------------------------------------
#define VIT_SMEM (96*96*4 + 2*96*4 + 255*96 + 64)

__global__ __launch_bounds__(128)
void viterbi_kernel(float* __restrict__ potF, const float* __restrict__ potB,
                    const float* __restrict__ trans, float* __restrict__ dec)
{
    extern __shared__ float sm[];
    float* tS  = sm;               // [96][96]
    float* al  = tS + 96 * 96;     // [96]
    float* al2 = al + 96;          // [96]
    unsigned char* bp = (unsigned char*)(al2 + 96);  // [255][96]
    const int tid = threadIdx.x;
    const int b = blockIdx.x;

    for (int i = tid; i < 96 * 96; i += 128) tS[i] = trans[i];
    if (tid < 96) {
        size_t i0 = ((size_t)b * TT) * 96 + tid;
        float p0 = potF[i0] + potB[i0];
        potF[i0] = p0;
        al[tid] = p0;
    }
    __syncthreads();

    for (int t = 1; t < TT; t++) {
        if (tid < 96) {
            float best = -1e30f; int bi = 0;
#pragma unroll 4
            for (int i = 0; i < 96; i++) {
                float sc = al[i] + tS[i * 96 + tid];
                if (sc > best) { best = sc; bi = i; }
            }
            size_t idx = ((size_t)b * TT + t) * 96 + tid;
            float p = potF[idx] + potB[idx];
            potF[idx] = p;
            al2[tid] = best + p;
            bp[(t - 1) * 96 + tid] = (unsigned char)bi;
        }
        __syncthreads();
        if (tid < 96) al[tid] = al2[tid];
        __syncthreads();
    }
    if (tid == 0) {
        int bestj = 0; float bv = al[0];
        for (int j = 1; j < 96; j++) if (al[j] > bv) { bv = al[j]; bestj = j; }
        int tag = bestj;
        dec[(size_t)b * TT + TT - 1] = (float)tag;
        for (int t = TT - 2; t >= 0; t--) {
            tag = bp[t * 96 + tag];
            dec[(size_t)b * TT + t] = (float)tag;
        }
    }
}

// ---------------------------------------------------------------------------
extern "C" void kernel_launch(void* const* d_in, const int* in_sizes, int n_in,
                              void* d_out, int out_size)
{
    const float* x    = (const float*)d_in[0];
    const float* Wi1f = (const float*)d_in[1];
    const float* Wh1f = (const float*)d_in[2];
    const float* b1f  = (const float*)d_in[3];
    const float* Wi2f = (const float*)d_in[4];
    const float* Wh2f = (const float*)d_in[5];
    const float* b2f  = (const float*)d_in[6];
    const float* Wi1b = (const float*)d_in[7];
    const float* Wh1b = (const float*)d_in[8];
    const float* b1b  = (const float*)d_in[9];
    const float* Wi2b = (const float*)d_in[10];
    const float* Wh2b = (const float*)d_in[11];
    const float* b2b  = (const float*)d_in[12];
    const float* Wif  = (const float*)d_in[13];
    const float* Whf  = (const float*)d_in[14];
    const float* bf   = (const float*)d_in[15];
    const float* Wib  = (const float*)d_in[16];
    const float* Whb  = (const float*)d_in[17];
    const float* bb   = (const float*)d_in[18];
    const float* trans= (const float*)d_in[19];

    float* dec = (float*)d_out;           // decoded as float, B*T
    float* pot = (float*)d_out + BT;      // potentials, B*T*C

    float *xg1f, *xg1b, *xg2f, *xg2b, *h1f, *h1b, *hcat, *xgFf, *xgBf, *potB, *hst;
    cudaGetSymbolAddress((void**)&xg1f, g_xg1f);
    cudaGetSymbolAddress((void**)&xg1b, g_xg1b);
    cudaGetSymbolAddress((void**)&xg2f, g_xg2f);
    cudaGetSymbolAddress((void**)&xg2b, g_xg2b);
    cudaGetSymbolAddress((void**)&h1f,  g_h1f);
    cudaGetSymbolAddress((void**)&h1b,  g_h1b);
    cudaGetSymbolAddress((void**)&hcat, g_hcat);
    cudaGetSymbolAddress((void**)&xgFf, g_xgFf);
    cudaGetSymbolAddress((void**)&xgBf, g_xgBf);
    cudaGetSymbolAddress((void**)&potB, g_potB);
    cudaGetSymbolAddress((void**)&hst,  g_hstate);

    cudaFuncSetAttribute(scan_persist_kernel,
                         cudaFuncAttributeMaxDynamicSharedMemorySize, SCAN_SMEM);
    cudaFuncSetAttribute(final_lstm_kernel,
                         cudaFuncAttributeMaxDynamicSharedMemorySize, FIN_SMEM);
    cudaFuncSetAttribute(viterbi_kernel,
                         cudaFuncAttributeMaxDynamicSharedMemorySize, VIT_SMEM);

    dim3 g1(1024 / 64, BT / 128);   // (16, 256)
    gemm_bias_kernel<<<g1, 256>>>(x, Wi1f, b1f, xg1f, BT, 1024, 512);
    gemm_bias_kernel<<<g1, 256>>>(x, Wi1b, b1b, xg1b, BT, 1024, 512);

    dim3 gs(8, 8, 2);
    cudaMemsetAsync(hst, 0, sizeof(float) * 2 * 2 * HH * BB);
    reset_bar_kernel<<<1, 1>>>();
    scan_persist_kernel<<<gs, 256, SCAN_SMEM>>>(xg1f, xg1b, Wh1f, Wh1b,
                                                h1f, h1b, 256, 0, 0);

    gemm_bias_kernel<<<g1, 256>>>(h1f, Wi2f, b2f, xg2f, BT, 1024, 256);
    gemm_bias_kernel<<<g1, 256>>>(h1b, Wi2b, b2b, xg2b, BT, 1024, 256);

    cudaMemsetAsync(hst, 0, sizeof(float) * 2 * 2 * HH * BB);
    reset_bar_kernel<<<1, 1>>>();
    scan_persist_kernel<<<gs, 256, SCAN_SMEM>>>(xg2f, xg2b, Wh2f, Wh2b,
                                                hcat, hcat, 512, 0, 256);

    dim3 g2(384 / 64, BT / 128);    // (6, 256)
    gemm_bias_kernel<<<g2, 256>>>(hcat, Wif, bf, xgFf, BT, 384, 512);
    gemm_bias_kernel<<<g2, 256>>>(hcat, Wib, bb, xgBf, BT, 384, 512);

    dim3 gf(BB, 2);
    final_lstm_kernel<<<gf, 384, FIN_SMEM>>>(xgFf, xgBf, Whf, Whb, pot, potB);
    viterbi_kernel<<<BB, 128, VIT_SMEM>>>(pot, potB, trans, dec);
}

// round 8
// speedup vs baseline: 1.3329x; 1.0198x over previous
#include <cuda_runtime.h>
#include <math.h>

#define BB 128
#define TT 256
#define DD 512
#define HH 256
#define NC 96
#define BT (BB*TT)

// ---------------- scratch (static device globals; no runtime alloc) --------
__device__ float g_xg1f[(size_t)BT*1024];
__device__ float g_xg1b[(size_t)BT*1024];
__device__ float g_xg2f[(size_t)BT*1024];
__device__ float g_xg2b[(size_t)BT*1024];
__device__ float g_h1f[(size_t)BT*HH];
__device__ float g_h1b[(size_t)BT*HH];
__device__ float g_hcat[(size_t)BT*2*HH];
__device__ float g_xgFf[(size_t)BT*384];
__device__ float g_xgBf[(size_t)BT*384];
__device__ float g_potB[(size_t)BT*NC];
__device__ float g_hstate[2*2*HH*BB];     // [buf][dir][u][b]
// 16 group barrier counters (8 CTAs each), padded 256B apart
__device__ unsigned g_cnt[16*64];

// ---------------------------------------------------------------------------
// GEMM: C[M,N] = A[M,K] @ B[K,N] + bias[N]   fp32, tile 128x64, BK=16,
// inner loop uses packed fma.rn.f32x2 (row pairs), bit-identical to scalar FMA.
// ---------------------------------------------------------------------------
__global__ __launch_bounds__(256)
void gemm_bias_kernel(const float* __restrict__ A, const float* __restrict__ Bm,
                      const float* __restrict__ bias, float* __restrict__ C,
                      int M, int N, int K)
{
    __shared__ float As[16][132];   // As[k][m]
    __shared__ float Bs[16][64];

    const int tid  = threadIdx.x;
    const int m0   = blockIdx.y * 128;
    const int n0   = blockIdx.x * 64;
    const int trow = tid >> 4;      // 0..15 -> rows trow*8..+7
    const int tcol = tid & 15;      // 0..15 -> cols tcol*4..+3

    unsigned long long acc[4][4];   // [row-pair p -> rows 2p,2p+1][col j]
#pragma unroll
    for (int p = 0; p < 4; p++)
#pragma unroll
        for (int j = 0; j < 4; j++) acc[p][j] = 0ull;

    for (int k0 = 0; k0 < K; k0 += 16) {
#pragma unroll
        for (int i = 0; i < 8; i++) {
            int lin = i * 256 + tid;                 // 2048 = 128 rows x 16 k
            int r = lin >> 4, kk = lin & 15;
            As[kk][r] = A[(size_t)(m0 + r) * K + k0 + kk];
        }
#pragma unroll
        for (int i = 0; i < 4; i++) {
            int lin = i * 256 + tid;                 // 1024 = 16 k x 64 n
            int kk = lin >> 6, c = lin & 63;
            Bs[kk][c] = Bm[(size_t)(k0 + kk) * N + n0 + c];
        }
        __syncthreads();
#pragma unroll
        for (int kk = 0; kk < 16; kk++) {
            ulonglong2 aP0 = *(const ulonglong2*)&As[kk][trow * 8];      // (r0,r1),(r2,r3)
            ulonglong2 aP1 = *(const ulonglong2*)&As[kk][trow * 8 + 4];  // (r4,r5),(r6,r7)
            float4 b0 = *(const float4*)&Bs[kk][tcol * 4];
            unsigned long long bd0, bd1, bd2, bd3;
            asm("mov.b64 %0, {%1, %1};" : "=l"(bd0) : "f"(b0.x));
            asm("mov.b64 %0, {%1, %1};" : "=l"(bd1) : "f"(b0.y));
            asm("mov.b64 %0, {%1, %1};" : "=l"(bd2) : "f"(b0.z));
            asm("mov.b64 %0, {%1, %1};" : "=l"(bd3) : "f"(b0.w));
            unsigned long long ap[4] = {aP0.x, aP0.y, aP1.x, aP1.y};
            unsigned long long bd[4] = {bd0, bd1, bd2, bd3};
#pragma unroll
            for (int p = 0; p < 4; p++)
#pragma unroll
                for (int j = 0; j < 4; j++)
                    asm("fma.rn.f32x2 %0, %1, %2, %0;"
                        : "+l"(acc[p][j]) : "l"(ap[p]), "l"(bd[j]));
        }
        __syncthreads();
    }

    float bz[4];
#pragma unroll
    for (int j = 0; j < 4; j++) bz[j] = bias[n0 + tcol * 4 + j];
#pragma unroll
    for (int p = 0; p < 4; p++) {
        float lo[4], hi[4];
#pragma unroll
        for (int j = 0; j < 4; j++)
            asm("mov.b64 {%0, %1}, %2;" : "=f"(lo[j]), "=f"(hi[j]) : "l"(acc[p][j]));
        size_t r0 = m0 + trow * 8 + 2 * p;
        float4 v0, v1;
        v0.x = lo[0] + bz[0]; v0.y = lo[1] + bz[1]; v0.z = lo[2] + bz[2]; v0.w = lo[3] + bz[3];
        v1.x = hi[0] + bz[0]; v1.y = hi[1] + bz[1]; v1.z = hi[2] + bz[2]; v1.w = hi[3] + bz[3];
        *(float4*)&C[r0 * N + n0 + tcol * 4] = v0;
        *(float4*)&C[(r0 + 1) * N + n0 + tcol * 4] = v1;
    }
}

// ---------------------------------------------------------------------------
__global__ void reset_bar_kernel()
{
    int i = threadIdx.x;
    if (i < 16) g_cnt[i * 64] = 0u;
}

// ---------------------------------------------------------------------------
// Persistent dual-direction LSTM scan (H=256, tanh). Grid (8,8,2) = 128 CTAs,
// 1 CTA/SM (152.5KB smem) -> all co-resident. Per-step sync: counting barrier
// over the 8 CTAs sharing (b0, dir). Arrive = __threadfence (release) +
// atomicAdd (strong RMW). Wait = poll the SAME counter with a STRONG acquire
// load (ld.acquire.gpu) -- morally-strong observation, so the release-acquire
// chain over all arrivers' h-writes is valid per the PTX memory model.
// (R6/R7 polled a separate flag with a WEAK ld.global.cg: no sync edge -> race.)
// Wh staged in smem once; h double-buffered in global via stcg/ldcg; c in regs.
// ---------------------------------------------------------------------------
#define SCAN_SMEM ((256*128 + 256*16 + 128*17) * 4)

__global__ __launch_bounds__(256, 1)
void scan_persist_kernel(const float* __restrict__ xgF, const float* __restrict__ xgB,
                         const float* __restrict__ WhF, const float* __restrict__ WhB,
                         float* __restrict__ outF, float* __restrict__ outB,
                         int outStride, int offF, int offB)
{
    extern __shared__ float sm[];
    float* Ws = sm;                 // [256 k][128 c]
    float* hT = Ws + 256 * 128;     // [256 k][16 b]
    float* zS = hT + 256 * 16;      // [128 c][17]

    const int tid = threadIdx.x;
    const int u0  = blockIdx.x * 32;
    const int b0  = blockIdx.y * 16;
    const int dir = blockIdx.z;
    const float* Wh = dir ? WhB : WhF;
    const float* xg = dir ? xgB : xgF;
    float* out = dir ? outB : outF;
    const int off = dir ? offB : offF;
    unsigned* cnt = &g_cnt[(dir * 8 + blockIdx.y) * 64];   // padded barrier slot

    // stage Wh slice once: Ws[k][g*32+q] = Wh[k][g*256+u0+q]
#pragma unroll
    for (int i = 0; i < 32; i++) {
        int v = i * 256 + tid;              // float4 index, 8192 total
        int k = v >> 5, c4 = v & 31;
        int gate = c4 >> 3, q = c4 & 7;
        float4 w = *(const float4*)(Wh + (size_t)k * 1024 + gate * 256 + u0 + q * 4);
        *(float4*)(Ws + k * 128 + gate * 32 + q * 4) = w;
    }

    const int tx = tid & 63;            // c pair index (2 cols)
    const int ty = tid >> 6;            // b quad index (4 rows)
    const float* hp = hT + ty * 4;
    const float* wp = Ws + tx * 2;
    const int gb = tid >> 4;            // gate-phase batch 0..15
    const int gu = tid & 15;            // gate-phase unit 0..15
    const int bg = b0 + gb;
    float creg0 = 0.0f, creg1 = 0.0f;

#pragma unroll 1
    for (int s = 0; s < TT; s++) {
        const int t = dir ? (TT - 1 - s) : s;
        const float* hr = g_hstate + (size_t)(s & 1) * (2 * HH * BB) + dir * (HH * BB);
        float*       hw = g_hstate + (size_t)((s + 1) & 1) * (2 * HH * BB) + dir * (HH * BB);

        // prefetch this thread's xg gate inputs (hides DRAM latency under z compute)
        const size_t xrow = ((size_t)bg * TT + t) * 1024;
        float xv[8];
#pragma unroll
        for (int i = 0; i < 2; i++) {
            int u = u0 + gu + 16 * i;
            xv[i * 4 + 0] = xg[xrow + 0 * 256 + u];
            xv[i * 4 + 1] = xg[xrow + 1 * 256 + u];
            xv[i * 4 + 2] = xg[xrow + 2 * 256 + u];
            xv[i * 4 + 3] = xg[xrow + 3 * 256 + u];
        }

        // stage h (previous step, group CTAs' writes) via L2
#pragma unroll
        for (int i = 0; i < 4; i++) {
            int v = i * 256 + tid;
            int k = v >> 2, b4 = v & 3;
            float4 h = __ldcg((const float4*)(hr + k * 128 + b0 + b4 * 4));
            *(float4*)(hT + k * 16 + b4 * 4) = h;
        }
        __syncthreads();

        // z = h @ Wh, packed f32x2 over b pairs
        unsigned long long pA = 0ull, pB = 0ull, pC = 0ull, pD = 0ull;
#pragma unroll 4
        for (int k = 0; k < 256; k++) {
            ulonglong2 hv = *(const ulonglong2*)(hp + k * 16);   // (b0,b1),(b2,b3)
            float2 w2 = *(const float2*)(wp + k * 128);
            unsigned long long wxx, wyy;
            asm("mov.b64 %0, {%1, %1};" : "=l"(wxx) : "f"(w2.x));
            asm("mov.b64 %0, {%1, %1};" : "=l"(wyy) : "f"(w2.y));
            asm("fma.rn.f32x2 %0, %1, %2, %0;" : "+l"(pA) : "l"(hv.x), "l"(wxx));
            asm("fma.rn.f32x2 %0, %1, %2, %0;" : "+l"(pB) : "l"(hv.y), "l"(wxx));
            asm("fma.rn.f32x2 %0, %1, %2, %0;" : "+l"(pC) : "l"(hv.x), "l"(wyy));
            asm("fma.rn.f32x2 %0, %1, %2, %0;" : "+l"(pD) : "l"(hv.y), "l"(wyy));
        }
        {
            float a00, a10, a20, a30, a01, a11, a21, a31;
            asm("mov.b64 {%0, %1}, %2;" : "=f"(a00), "=f"(a10) : "l"(pA));
            asm("mov.b64 {%0, %1}, %2;" : "=f"(a20), "=f"(a30) : "l"(pB));
            asm("mov.b64 {%0, %1}, %2;" : "=f"(a01), "=f"(a11) : "l"(pC));
            asm("mov.b64 {%0, %1}, %2;" : "=f"(a21), "=f"(a31) : "l"(pD));
            int c0 = tx * 2, r = ty * 4;
            zS[c0 * 17 + r + 0] = a00; zS[(c0 + 1) * 17 + r + 0] = a01;
            zS[c0 * 17 + r + 1] = a10; zS[(c0 + 1) * 17 + r + 1] = a11;
            zS[c0 * 17 + r + 2] = a20; zS[(c0 + 1) * 17 + r + 2] = a21;
            zS[c0 * 17 + r + 3] = a30; zS[(c0 + 1) * 17 + r + 3] = a31;
        }
        __syncthreads();

        // gates
#pragma unroll
        for (int i = 0; i < 2; i++) {
            int ul = gu + 16 * i;
            int u  = u0 + ul;
            float zi = zS[(0 * 32 + ul) * 17 + gb] + xv[i * 4 + 0];
            float zf = zS[(1 * 32 + ul) * 17 + gb] + xv[i * 4 + 1];
            float zg = zS[(2 * 32 + ul) * 17 + gb] + xv[i * 4 + 2];
            float zo = zS[(3 * 32 + ul) * 17 + gb] + xv[i * 4 + 3];
            float iv = 1.f / (1.f + expf(-zi));
            float fv = 1.f / (1.f + expf(-zf));
            float ov = 1.f / (1.f + expf(-zo));
            float cold = i ? creg1 : creg0;
            float cn = fv * cold + iv * tanhf(zg);
            float hn = ov * tanhf(cn);
            if (i) creg1 = cn; else creg0 = cn;
            __stcg(hw + (size_t)u * BB + bg, hn);
            out[((size_t)bg * TT + t) * outStride + off + u] = hn;
        }

        // group counting barrier: release-fence + arrive RMW; wait by polling
        // the counter with a STRONG acquire load (synchronizes-with arrivers).
        __syncthreads();
        if (tid == 0) {
            __threadfence();                       // release this CTA's h writes
            atomicAdd(cnt, 1u);
            unsigned tgt = (unsigned)(s + 1) * 8u;
            unsigned f;
            do {
                asm volatile("ld.acquire.gpu.global.u32 %0, [%1];"
                             : "=r"(f) : "l"(cnt) : "memory");
            } while (f < tgt);
        }
        __syncthreads();
    }
}

// ---------------------------------------------------------------------------
// Final LSTMs (C=96, softmax activation), one CTA per (sample, direction).
// dir 0 writes pot (d_out area), dir 1 writes g_potB; Viterbi fuses the sum.
// ---------------------------------------------------------------------------
__device__ __forceinline__ float blockReduce96(float v, bool isMax,
                                               volatile float* red, int tid)
{
#pragma unroll
    for (int o = 16; o > 0; o >>= 1) {
        float w = __shfl_down_sync(0xffffffffu, v, o);
        v = isMax ? fmaxf(v, w) : v + w;
    }
    if (tid < 96 && (tid & 31) == 0) red[tid >> 5] = v;
    __syncthreads();
    float r = isMax ? fmaxf(fmaxf(red[0], red[1]), red[2])
                    : red[0] + red[1] + red[2];
    __syncthreads();
    return r;
}

#define FIN_SMEM ((96*384 + 384 + 96 + 96 + 4) * 4)

__global__ __launch_bounds__(384)
void final_lstm_kernel(const float* __restrict__ xgF, const float* __restrict__ xgB,
                       const float* __restrict__ WhF, const float* __restrict__ WhB,
                       float* __restrict__ potF, float* __restrict__ potB)
{
    extern __shared__ float sm[];
    float* WhS = sm;              // [96][384]
    float* zS  = WhS + 96 * 384;  // [384]
    float* hS  = zS + 384;        // [96]
    float* cS  = hS + 96;         // [96]
    float* red = cS + 96;         // [4]
    const int tid = threadIdx.x;
    const int b = blockIdx.x;
    const int dir = blockIdx.y;

    const float* Wh = dir ? WhB : WhF;
    const float* xg = dir ? xgB : xgF;
    float* pot = dir ? potB : potF;

    for (int i = tid; i < 96 * 384; i += 384) WhS[i] = Wh[i];
    if (tid < 96) { hS[tid] = 0.f; cS[tid] = 0.f; }
    __syncthreads();

    for (int s = 0; s < TT; s++) {
        int t = dir ? (TT - 1 - s) : s;
        float a = xg[((size_t)b * TT + t) * 384 + tid];
#pragma unroll 4
        for (int k = 0; k < 96; k++) a += hS[k] * WhS[k * 384 + tid];
        zS[tid] = a;
        __syncthreads();

        bool v = tid < 96;
        float gv = v ? zS[192 + tid] : -1e30f;
        float gmax = blockReduce96(gv, true, red, tid);
        float ge = v ? expf(gv - gmax) : 0.f;
        float gsum = blockReduce96(ge, false, red, tid);
        float cn = 0.f;
        if (v) {
            float iv = 1.f / (1.f + expf(-zS[tid]));
            float fv = 1.f / (1.f + expf(-zS[96 + tid]));
            cn = fv * cS[tid] + iv * (ge / gsum);
        }
        float cmax = blockReduce96(v ? cn : -1e30f, true, red, tid);
        float ce = v ? expf(cn - cmax) : 0.f;
        float csum = blockReduce96(ce, false, red, tid);
        if (v) {
            float ov = 1.f / (1.f + expf(-zS[288 + tid]));
            float hv = ov * (ce / csum);
            cS[tid] = cn;
            hS[tid] = hv;
            pot[((size_t)b * TT + t) * 96 + tid] = hv;
        }
        __syncthreads();
    }
}

// ---------------------------------------------------------------------------
// Viterbi: one CTA per sample. Fuses pot = pf + pb (writes summed pot to d_out).
// Strict-> comparisons = jnp.argmax first-max tie-breaking.
// ---------------------------------------------------------------------------
#define VIT_SMEM (96*96*4 + 2*96*4 + 255*96 + 64)

__global__ __launch_bounds__(128)
void viterbi_kernel(float* __restrict__ potF, const float* __restrict__ potB,
                    const float* __restrict__ trans, float* __restrict__ dec)
{
    extern __shared__ float sm[];
    float* tS  = sm;               // [96][96]
    float* al  = tS + 96 * 96;     // [96]
    float* al2 = al + 96;          // [96]
    unsigned char* bp = (unsigned char*)(al2 + 96);  // [255][96]
    const int tid = threadIdx.x;
    const int b = blockIdx.x;

    for (int i = tid; i < 96 * 96; i += 128) tS[i] = trans[i];
    if (tid < 96) {
        size_t i0 = ((size_t)b * TT) * 96 + tid;
        float p0 = potF[i0] + potB[i0];
        potF[i0] = p0;
        al[tid] = p0;
    }
    __syncthreads();

    for (int t = 1; t < TT; t++) {
        if (tid < 96) {
            float best = -1e30f; int bi = 0;
#pragma unroll 4
            for (int i = 0; i < 96; i++) {
                float sc = al[i] + tS[i * 96 + tid];
                if (sc > best) { best = sc; bi = i; }
            }
            size_t idx = ((size_t)b * TT + t) * 96 + tid;
            float p = potF[idx] + potB[idx];
            potF[idx] = p;
            al2[tid] = best + p;
            bp[(t - 1) * 96 + tid] = (unsigned char)bi;
        }
        __syncthreads();
        if (tid < 96) al[tid] = al2[tid];
        __syncthreads();
    }
    if (tid == 0) {
        int bestj = 0; float bv = al[0];
        for (int j = 1; j < 96; j++) if (al[j] > bv) { bv = al[j]; bestj = j; }
        int tag = bestj;
        dec[(size_t)b * TT + TT - 1] = (float)tag;
        for (int t = TT - 2; t >= 0; t--) {
            tag = bp[t * 96 + tag];
            dec[(size_t)b * TT + t] = (float)tag;
        }
    }
}

// ---------------------------------------------------------------------------
extern "C" void kernel_launch(void* const* d_in, const int* in_sizes, int n_in,
                              void* d_out, int out_size)
{
    const float* x    = (const float*)d_in[0];
    const float* Wi1f = (const float*)d_in[1];
    const float* Wh1f = (const float*)d_in[2];
    const float* b1f  = (const float*)d_in[3];
    const float* Wi2f = (const float*)d_in[4];
    const float* Wh2f = (const float*)d_in[5];
    const float* b2f  = (const float*)d_in[6];
    const float* Wi1b = (const float*)d_in[7];
    const float* Wh1b = (const float*)d_in[8];
    const float* b1b  = (const float*)d_in[9];
    const float* Wi2b = (const float*)d_in[10];
    const float* Wh2b = (const float*)d_in[11];
    const float* b2b  = (const float*)d_in[12];
    const float* Wif  = (const float*)d_in[13];
    const float* Whf  = (const float*)d_in[14];
    const float* bf   = (const float*)d_in[15];
    const float* Wib  = (const float*)d_in[16];
    const float* Whb  = (const float*)d_in[17];
    const float* bb   = (const float*)d_in[18];
    const float* trans= (const float*)d_in[19];

    float* dec = (float*)d_out;           // decoded as float, B*T
    float* pot = (float*)d_out + BT;      // potentials, B*T*C

    float *xg1f, *xg1b, *xg2f, *xg2b, *h1f, *h1b, *hcat, *xgFf, *xgBf, *potB, *hst;
    cudaGetSymbolAddress((void**)&xg1f, g_xg1f);
    cudaGetSymbolAddress((void**)&xg1b, g_xg1b);
    cudaGetSymbolAddress((void**)&xg2f, g_xg2f);
    cudaGetSymbolAddress((void**)&xg2b, g_xg2b);
    cudaGetSymbolAddress((void**)&h1f,  g_h1f);
    cudaGetSymbolAddress((void**)&h1b,  g_h1b);
    cudaGetSymbolAddress((void**)&hcat, g_hcat);
    cudaGetSymbolAddress((void**)&xgFf, g_xgFf);
    cudaGetSymbolAddress((void**)&xgBf, g_xgBf);
    cudaGetSymbolAddress((void**)&potB, g_potB);
    cudaGetSymbolAddress((void**)&hst,  g_hstate);

    cudaFuncSetAttribute(scan_persist_kernel,
                         cudaFuncAttributeMaxDynamicSharedMemorySize, SCAN_SMEM);
    cudaFuncSetAttribute(final_lstm_kernel,
                         cudaFuncAttributeMaxDynamicSharedMemorySize, FIN_SMEM);
    cudaFuncSetAttribute(viterbi_kernel,
                         cudaFuncAttributeMaxDynamicSharedMemorySize, VIT_SMEM);

    dim3 g1(1024 / 64, BT / 128);   // (16, 256)
    gemm_bias_kernel<<<g1, 256>>>(x, Wi1f, b1f, xg1f, BT, 1024, 512);
    gemm_bias_kernel<<<g1, 256>>>(x, Wi1b, b1b, xg1b, BT, 1024, 512);

    dim3 gs(8, 8, 2);
    cudaMemsetAsync(hst, 0, sizeof(float) * 2 * 2 * HH * BB);
    reset_bar_kernel<<<1, 32>>>();
    scan_persist_kernel<<<gs, 256, SCAN_SMEM>>>(xg1f, xg1b, Wh1f, Wh1b,
                                                h1f, h1b, 256, 0, 0);

    gemm_bias_kernel<<<g1, 256>>>(h1f, Wi2f, b2f, xg2f, BT, 1024, 256);
    gemm_bias_kernel<<<g1, 256>>>(h1b, Wi2b, b2b, xg2b, BT, 1024, 256);

    cudaMemsetAsync(hst, 0, sizeof(float) * 2 * 2 * HH * BB);
    reset_bar_kernel<<<1, 32>>>();
    scan_persist_kernel<<<gs, 256, SCAN_SMEM>>>(xg2f, xg2b, Wh2f, Wh2b,
                                                hcat, hcat, 512, 0, 256);

    dim3 g2(384 / 64, BT / 128);    // (6, 256)
    gemm_bias_kernel<<<g2, 256>>>(hcat, Wif, bf, xgFf, BT, 384, 512);
    gemm_bias_kernel<<<g2, 256>>>(hcat, Wib, bb, xgBf, BT, 384, 512);

    dim3 gf(BB, 2);
    final_lstm_kernel<<<gf, 384, FIN_SMEM>>>(xgFf, xgBf, Whf, Whb, pot, potB);
    viterbi_kernel<<<BB, 128, VIT_SMEM>>>(pot, potB, trans, dec);
}

// round 9
// speedup vs baseline: 1.3536x; 1.0155x over previous
#include <cuda_runtime.h>
#include <math.h>

#define BB 128
#define TT 256
#define DD 512
#define HH 256
#define NC 96
#define BT (BB*TT)

// ---------------- scratch (static device globals; no runtime alloc) --------
__device__ float g_xg1f[(size_t)BT*1024];
__device__ float g_xg1b[(size_t)BT*1024];
__device__ float g_xg2f[(size_t)BT*1024];
__device__ float g_xg2b[(size_t)BT*1024];
__device__ float g_h1f[(size_t)BT*HH];
__device__ float g_h1b[(size_t)BT*HH];
__device__ float g_hcat[(size_t)BT*2*HH];
__device__ float g_xgFf[(size_t)BT*384];
__device__ float g_xgBf[(size_t)BT*384];
__device__ float g_potB[(size_t)BT*NC];
__device__ float g_hstate[2*2*HH*BB];     // [buf][dir][u][b]
// 16 group barrier counters (8 CTAs each), padded 256B apart
__device__ unsigned g_cnt[16*64];

// ---------------------------------------------------------------------------
// GEMM v2: C[M,N] = A[M,K] @ B[K,N] + bias[N].  fp32, tile 128x128, BK=16,
// 256 threads, 8x8 outputs/thread, register-prefetch double buffering,
// packed fma.rn.f32x2 (bit-identical to scalar FFMA).
// Requires: M%128==0, N%128==0, K%16==0.
// ---------------------------------------------------------------------------
__global__ __launch_bounds__(256, 2)
void gemm_bias_kernel(const float* __restrict__ A, const float* __restrict__ Bm,
                      const float* __restrict__ bias, float* __restrict__ C,
                      int M, int N, int K)
{
    __shared__ float As[16][132];   // [k][m], padded
    __shared__ float Bs[16][128];   // [k][n]

    const int tid = threadIdx.x;
    const int m0  = blockIdx.y * 128;
    const int n0  = blockIdx.x * 128;
    const int txn = tid & 15;       // n block: cols txn*8..+7
    const int tym = tid >> 4;       // m block: rows tym*8..+7

    // A-load mapping: lin in {tid, 256+tid}: row = lin>>2, kgrp = lin&3 (4 k)
    const int arow = tid >> 2;
    const int akg  = (tid & 3) * 4;
    // B-load mapping: lin in {tid, 256+tid}: kk = lin>>5, n4 = lin&31
    const int bkk = tid >> 5;
    const int bn  = (tid & 31) * 4;

    unsigned long long acc[4][8];   // [m-pair p -> rows 2p,2p+1][n j]
#pragma unroll
    for (int p = 0; p < 4; p++)
#pragma unroll
        for (int j = 0; j < 8; j++) acc[p][j] = 0ull;

    const int T = K / 16;
    float4 aR0, aR1, bR0, bR1;

    // prologue: tile 0 -> regs -> smem
    aR0 = *(const float4*)&A[(size_t)(m0 + arow) * K + akg];
    aR1 = *(const float4*)&A[(size_t)(m0 + 64 + arow) * K + akg];
    bR0 = *(const float4*)&Bm[(size_t)bkk * N + n0 + bn];
    bR1 = *(const float4*)&Bm[(size_t)(8 + bkk) * N + n0 + bn];
    {
        As[akg + 0][arow] = aR0.x; As[akg + 1][arow] = aR0.y;
        As[akg + 2][arow] = aR0.z; As[akg + 3][arow] = aR0.w;
        As[akg + 0][64 + arow] = aR1.x; As[akg + 1][64 + arow] = aR1.y;
        As[akg + 2][64 + arow] = aR1.z; As[akg + 3][64 + arow] = aR1.w;
        *(float4*)&Bs[bkk][bn] = bR0;
        *(float4*)&Bs[8 + bkk][bn] = bR1;
    }
    __syncthreads();

    for (int t = 0; t < T; t++) {
        // prefetch next tile into registers (latency hidden under compute)
        if (t + 1 < T) {
            int k0 = (t + 1) * 16;
            aR0 = *(const float4*)&A[(size_t)(m0 + arow) * K + k0 + akg];
            aR1 = *(const float4*)&A[(size_t)(m0 + 64 + arow) * K + k0 + akg];
            bR0 = *(const float4*)&Bm[(size_t)(k0 + bkk) * N + n0 + bn];
            bR1 = *(const float4*)&Bm[(size_t)(k0 + 8 + bkk) * N + n0 + bn];
        }
#pragma unroll
        for (int kk = 0; kk < 16; kk++) {
            ulonglong2 aP0 = *(const ulonglong2*)&As[kk][tym * 8];      // (m0,m1),(m2,m3)
            ulonglong2 aP1 = *(const ulonglong2*)&As[kk][tym * 8 + 4];  // (m4,m5),(m6,m7)
            float4 b0 = *(const float4*)&Bs[kk][txn * 8];
            float4 b1 = *(const float4*)&Bs[kk][txn * 8 + 4];
            unsigned long long bd[8];
            asm("mov.b64 %0, {%1, %1};" : "=l"(bd[0]) : "f"(b0.x));
            asm("mov.b64 %0, {%1, %1};" : "=l"(bd[1]) : "f"(b0.y));
            asm("mov.b64 %0, {%1, %1};" : "=l"(bd[2]) : "f"(b0.z));
            asm("mov.b64 %0, {%1, %1};" : "=l"(bd[3]) : "f"(b0.w));
            asm("mov.b64 %0, {%1, %1};" : "=l"(bd[4]) : "f"(b1.x));
            asm("mov.b64 %0, {%1, %1};" : "=l"(bd[5]) : "f"(b1.y));
            asm("mov.b64 %0, {%1, %1};" : "=l"(bd[6]) : "f"(b1.z));
            asm("mov.b64 %0, {%1, %1};" : "=l"(bd[7]) : "f"(b1.w));
            unsigned long long ap[4] = {aP0.x, aP0.y, aP1.x, aP1.y};
#pragma unroll
            for (int p = 0; p < 4; p++)
#pragma unroll
                for (int j = 0; j < 8; j++)
                    asm("fma.rn.f32x2 %0, %1, %2, %0;"
                        : "+l"(acc[p][j]) : "l"(ap[p]), "l"(bd[j]));
        }
        __syncthreads();
        if (t + 1 < T) {
            As[akg + 0][arow] = aR0.x; As[akg + 1][arow] = aR0.y;
            As[akg + 2][arow] = aR0.z; As[akg + 3][arow] = aR0.w;
            As[akg + 0][64 + arow] = aR1.x; As[akg + 1][64 + arow] = aR1.y;
            As[akg + 2][64 + arow] = aR1.z; As[akg + 3][64 + arow] = aR1.w;
            *(float4*)&Bs[bkk][bn] = bR0;
            *(float4*)&Bs[8 + bkk][bn] = bR1;
            __syncthreads();
        }
    }

    float4 z0 = *(const float4*)&bias[n0 + txn * 8];
    float4 z1 = *(const float4*)&bias[n0 + txn * 8 + 4];
    float bz[8] = {z0.x, z0.y, z0.z, z0.w, z1.x, z1.y, z1.z, z1.w};
#pragma unroll
    for (int p = 0; p < 4; p++) {
        float lo[8], hi[8];
#pragma unroll
        for (int j = 0; j < 8; j++)
            asm("mov.b64 {%0, %1}, %2;" : "=f"(lo[j]), "=f"(hi[j]) : "l"(acc[p][j]));
        size_t r0 = (size_t)(m0 + tym * 8 + 2 * p) * N + n0 + txn * 8;
        size_t r1 = r0 + N;
        float4 v;
        v.x = lo[0] + bz[0]; v.y = lo[1] + bz[1]; v.z = lo[2] + bz[2]; v.w = lo[3] + bz[3];
        *(float4*)&C[r0] = v;
        v.x = lo[4] + bz[4]; v.y = lo[5] + bz[5]; v.z = lo[6] + bz[6]; v.w = lo[7] + bz[7];
        *(float4*)&C[r0 + 4] = v;
        v.x = hi[0] + bz[0]; v.y = hi[1] + bz[1]; v.z = hi[2] + bz[2]; v.w = hi[3] + bz[3];
        *(float4*)&C[r1] = v;
        v.x = hi[4] + bz[4]; v.y = hi[5] + bz[5]; v.z = hi[6] + bz[6]; v.w = hi[7] + bz[7];
        *(float4*)&C[r1 + 4] = v;
    }
}

// ---------------------------------------------------------------------------
__global__ void reset_bar_kernel()
{
    int i = threadIdx.x;
    if (i < 16) g_cnt[i * 64] = 0u;
}

// ---------------------------------------------------------------------------
// Persistent dual-direction LSTM scan (unchanged from passing R8).
// ---------------------------------------------------------------------------
#define SCAN_SMEM ((256*128 + 256*16 + 128*17) * 4)

__global__ __launch_bounds__(256, 1)
void scan_persist_kernel(const float* __restrict__ xgF, const float* __restrict__ xgB,
                         const float* __restrict__ WhF, const float* __restrict__ WhB,
                         float* __restrict__ outF, float* __restrict__ outB,
                         int outStride, int offF, int offB)
{
    extern __shared__ float sm[];
    float* Ws = sm;                 // [256 k][128 c]
    float* hT = Ws + 256 * 128;     // [256 k][16 b]
    float* zS = hT + 256 * 16;      // [128 c][17]

    const int tid = threadIdx.x;
    const int u0  = blockIdx.x * 32;
    const int b0  = blockIdx.y * 16;
    const int dir = blockIdx.z;
    const float* Wh = dir ? WhB : WhF;
    const float* xg = dir ? xgB : xgF;
    float* out = dir ? outB : outF;
    const int off = dir ? offB : offF;
    unsigned* cnt = &g_cnt[(dir * 8 + blockIdx.y) * 64];   // padded barrier slot

    // stage Wh slice once: Ws[k][g*32+q] = Wh[k][g*256+u0+q]
#pragma unroll
    for (int i = 0; i < 32; i++) {
        int v = i * 256 + tid;              // float4 index, 8192 total
        int k = v >> 5, c4 = v & 31;
        int gate = c4 >> 3, q = c4 & 7;
        float4 w = *(const float4*)(Wh + (size_t)k * 1024 + gate * 256 + u0 + q * 4);
        *(float4*)(Ws + k * 128 + gate * 32 + q * 4) = w;
    }

    const int tx = tid & 63;            // c pair index (2 cols)
    const int ty = tid >> 6;            // b quad index (4 rows)
    const float* hp = hT + ty * 4;
    const float* wp = Ws + tx * 2;
    const int gb = tid >> 4;            // gate-phase batch 0..15
    const int gu = tid & 15;            // gate-phase unit 0..15
    const int bg = b0 + gb;
    float creg0 = 0.0f, creg1 = 0.0f;

#pragma unroll 1
    for (int s = 0; s < TT; s++) {
        const int t = dir ? (TT - 1 - s) : s;
        const float* hr = g_hstate + (size_t)(s & 1) * (2 * HH * BB) + dir * (HH * BB);
        float*       hw = g_hstate + (size_t)((s + 1) & 1) * (2 * HH * BB) + dir * (HH * BB);

        // prefetch this thread's xg gate inputs (hides DRAM latency under z compute)
        const size_t xrow = ((size_t)bg * TT + t) * 1024;
        float xv[8];
#pragma unroll
        for (int i = 0; i < 2; i++) {
            int u = u0 + gu + 16 * i;
            xv[i * 4 + 0] = xg[xrow + 0 * 256 + u];
            xv[i * 4 + 1] = xg[xrow + 1 * 256 + u];
            xv[i * 4 + 2] = xg[xrow + 2 * 256 + u];
            xv[i * 4 + 3] = xg[xrow + 3 * 256 + u];
        }

        // stage h (previous step, group CTAs' writes) via L2
#pragma unroll
        for (int i = 0; i < 4; i++) {
            int v = i * 256 + tid;
            int k = v >> 2, b4 = v & 3;
            float4 h = __ldcg((const float4*)(hr + k * 128 + b0 + b4 * 4));
            *(float4*)(hT + k * 16 + b4 * 4) = h;
        }
        __syncthreads();

        // z = h @ Wh, packed f32x2 over b pairs
        unsigned long long pA = 0ull, pB = 0ull, pC = 0ull, pD = 0ull;
#pragma unroll 4
        for (int k = 0; k < 256; k++) {
            ulonglong2 hv = *(const ulonglong2*)(hp + k * 16);   // (b0,b1),(b2,b3)
            float2 w2 = *(const float2*)(wp + k * 128);
            unsigned long long wxx, wyy;
            asm("mov.b64 %0, {%1, %1};" : "=l"(wxx) : "f"(w2.x));
            asm("mov.b64 %0, {%1, %1};" : "=l"(wyy) : "f"(w2.y));
            asm("fma.rn.f32x2 %0, %1, %2, %0;" : "+l"(pA) : "l"(hv.x), "l"(wxx));
            asm("fma.rn.f32x2 %0, %1, %2, %0;" : "+l"(pB) : "l"(hv.y), "l"(wxx));
            asm("fma.rn.f32x2 %0, %1, %2, %0;" : "+l"(pC) : "l"(hv.x), "l"(wyy));
            asm("fma.rn.f32x2 %0, %1, %2, %0;" : "+l"(pD) : "l"(hv.y), "l"(wyy));
        }
        {
            float a00, a10, a20, a30, a01, a11, a21, a31;
            asm("mov.b64 {%0, %1}, %2;" : "=f"(a00), "=f"(a10) : "l"(pA));
            asm("mov.b64 {%0, %1}, %2;" : "=f"(a20), "=f"(a30) : "l"(pB));
            asm("mov.b64 {%0, %1}, %2;" : "=f"(a01), "=f"(a11) : "l"(pC));
            asm("mov.b64 {%0, %1}, %2;" : "=f"(a21), "=f"(a31) : "l"(pD));
            int c0 = tx * 2, r = ty * 4;
            zS[c0 * 17 + r + 0] = a00; zS[(c0 + 1) * 17 + r + 0] = a01;
            zS[c0 * 17 + r + 1] = a10; zS[(c0 + 1) * 17 + r + 1] = a11;
            zS[c0 * 17 + r + 2] = a20; zS[(c0 + 1) * 17 + r + 2] = a21;
            zS[c0 * 17 + r + 3] = a30; zS[(c0 + 1) * 17 + r + 3] = a31;
        }
        __syncthreads();

        // gates
#pragma unroll
        for (int i = 0; i < 2; i++) {
            int ul = gu + 16 * i;
            int u  = u0 + ul;
            float zi = zS[(0 * 32 + ul) * 17 + gb] + xv[i * 4 + 0];
            float zf = zS[(1 * 32 + ul) * 17 + gb] + xv[i * 4 + 1];
            float zg = zS[(2 * 32 + ul) * 17 + gb] + xv[i * 4 + 2];
            float zo = zS[(3 * 32 + ul) * 17 + gb] + xv[i * 4 + 3];
            float iv = 1.f / (1.f + expf(-zi));
            float fv = 1.f / (1.f + expf(-zf));
            float ov = 1.f / (1.f + expf(-zo));
            float cold = i ? creg1 : creg0;
            float cn = fv * cold + iv * tanhf(zg);
            float hn = ov * tanhf(cn);
            if (i) creg1 = cn; else creg0 = cn;
            __stcg(hw + (size_t)u * BB + bg, hn);
            out[((size_t)bg * TT + t) * outStride + off + u] = hn;
        }

        // group counting barrier: release-fence + arrive RMW; wait by polling
        // the counter with a STRONG acquire load (synchronizes-with arrivers).
        __syncthreads();
        if (tid == 0) {
            __threadfence();                       // release this CTA's h writes
            atomicAdd(cnt, 1u);
            unsigned tgt = (unsigned)(s + 1) * 8u;
            unsigned f;
            do {
                asm volatile("ld.acquire.gpu.global.u32 %0, [%1];"
                             : "=r"(f) : "l"(cnt) : "memory");
            } while (f < tgt);
        }
        __syncthreads();
    }
}

// ---------------------------------------------------------------------------
// Final LSTMs (C=96, softmax activation), one CTA per (sample, direction).
// ---------------------------------------------------------------------------
__device__ __forceinline__ float blockReduce96(float v, bool isMax,
                                               volatile float* red, int tid)
{
#pragma unroll
    for (int o = 16; o > 0; o >>= 1) {
        float w = __shfl_down_sync(0xffffffffu, v, o);
        v = isMax ? fmaxf(v, w) : v + w;
    }
    if (tid < 96 && (tid & 31) == 0) red[tid >> 5] = v;
    __syncthreads();
    float r = isMax ? fmaxf(fmaxf(red[0], red[1]), red[2])
                    : red[0] + red[1] + red[2];
    __syncthreads();
    return r;
}

#define FIN_SMEM ((96*384 + 384 + 96 + 96 + 4) * 4)

__global__ __launch_bounds__(384)
void final_lstm_kernel(const float* __restrict__ xgF, const float* __restrict__ xgB,
                       const float* __restrict__ WhF, const float* __restrict__ WhB,
                       float* __restrict__ potF, float* __restrict__ potB)
{
    extern __shared__ float sm[];
    float* WhS = sm;              // [96][384]
    float* zS  = WhS + 96 * 384;  // [384]
    float* hS  = zS + 384;        // [96]
    float* cS  = hS + 96;         // [96]
    float* red = cS + 96;         // [4]
    const int tid = threadIdx.x;
    const int b = blockIdx.x;
    const int dir = blockIdx.y;

    const float* Wh = dir ? WhB : WhF;
    const float* xg = dir ? xgB : xgF;
    float* pot = dir ? potB : potF;

    for (int i = tid; i < 96 * 384; i += 384) WhS[i] = Wh[i];
    if (tid < 96) { hS[tid] = 0.f; cS[tid] = 0.f; }
    __syncthreads();

    for (int s = 0; s < TT; s++) {
        int t = dir ? (TT - 1 - s) : s;
        float a = xg[((size_t)b * TT + t) * 384 + tid];
#pragma unroll 4
        for (int k = 0; k < 96; k++) a += hS[k] * WhS[k * 384 + tid];
        zS[tid] = a;
        __syncthreads();

        bool v = tid < 96;
        float gv = v ? zS[192 + tid] : -1e30f;
        float gmax = blockReduce96(gv, true, red, tid);
        float ge = v ? expf(gv - gmax) : 0.f;
        float gsum = blockReduce96(ge, false, red, tid);
        float cn = 0.f;
        if (v) {
            float iv = 1.f / (1.f + expf(-zS[tid]));
            float fv = 1.f / (1.f + expf(-zS[96 + tid]));
            cn = fv * cS[tid] + iv * (ge / gsum);
        }
        float cmax = blockReduce96(v ? cn : -1e30f, true, red, tid);
        float ce = v ? expf(cn - cmax) : 0.f;
        float csum = blockReduce96(ce, false, red, tid);
        if (v) {
            float ov = 1.f / (1.f + expf(-zS[288 + tid]));
            float hv = ov * (ce / csum);
            cS[tid] = cn;
            hS[tid] = hv;
            pot[((size_t)b * TT + t) * 96 + tid] = hv;
        }
        __syncthreads();
    }
}

// ---------------------------------------------------------------------------
// Viterbi: one CTA per sample. Fuses pot = pf + pb (writes summed pot to d_out).
// ---------------------------------------------------------------------------
#define VIT_SMEM (96*96*4 + 2*96*4 + 255*96 + 64)

__global__ __launch_bounds__(128)
void viterbi_kernel(float* __restrict__ potF, const float* __restrict__ potB,
                    const float* __restrict__ trans, float* __restrict__ dec)
{
    extern __shared__ float sm[];
    float* tS  = sm;               // [96][96]
    float* al  = tS + 96 * 96;     // [96]
    float* al2 = al + 96;          // [96]
    unsigned char* bp = (unsigned char*)(al2 + 96);  // [255][96]
    const int tid = threadIdx.x;
    const int b = blockIdx.x;

    for (int i = tid; i < 96 * 96; i += 128) tS[i] = trans[i];
    if (tid < 96) {
        size_t i0 = ((size_t)b * TT) * 96 + tid;
        float p0 = potF[i0] + potB[i0];
        potF[i0] = p0;
        al[tid] = p0;
    }
    __syncthreads();

    for (int t = 1; t < TT; t++) {
        if (tid < 96) {
            float best = -1e30f; int bi = 0;
#pragma unroll 4
            for (int i = 0; i < 96; i++) {
                float sc = al[i] + tS[i * 96 + tid];
                if (sc > best) { best = sc; bi = i; }
            }
            size_t idx = ((size_t)b * TT + t) * 96 + tid;
            float p = potF[idx] + potB[idx];
            potF[idx] = p;
            al2[tid] = best + p;
            bp[(t - 1) * 96 + tid] = (unsigned char)bi;
        }
        __syncthreads();
        if (tid < 96) al[tid] = al2[tid];
        __syncthreads();
    }
    if (tid == 0) {
        int bestj = 0; float bv = al[0];
        for (int j = 1; j < 96; j++) if (al[j] > bv) { bv = al[j]; bestj = j; }
        int tag = bestj;
        dec[(size_t)b * TT + TT - 1] = (float)tag;
        for (int t = TT - 2; t >= 0; t--) {
            tag = bp[t * 96 + tag];
            dec[(size_t)b * TT + t] = (float)tag;
        }
    }
}

// ---------------------------------------------------------------------------
extern "C" void kernel_launch(void* const* d_in, const int* in_sizes, int n_in,
                              void* d_out, int out_size)
{
    const float* x    = (const float*)d_in[0];
    const float* Wi1f = (const float*)d_in[1];
    const float* Wh1f = (const float*)d_in[2];
    const float* b1f  = (const float*)d_in[3];
    const float* Wi2f = (const float*)d_in[4];
    const float* Wh2f = (const float*)d_in[5];
    const float* b2f  = (const float*)d_in[6];
    const float* Wi1b = (const float*)d_in[7];
    const float* Wh1b = (const float*)d_in[8];
    const float* b1b  = (const float*)d_in[9];
    const float* Wi2b = (const float*)d_in[10];
    const float* Wh2b = (const float*)d_in[11];
    const float* b2b  = (const float*)d_in[12];
    const float* Wif  = (const float*)d_in[13];
    const float* Whf  = (const float*)d_in[14];
    const float* bf   = (const float*)d_in[15];
    const float* Wib  = (const float*)d_in[16];
    const float* Whb  = (const float*)d_in[17];
    const float* bb   = (const float*)d_in[18];
    const float* trans= (const float*)d_in[19];

    float* dec = (float*)d_out;           // decoded as float, B*T
    float* pot = (float*)d_out + BT;      // potentials, B*T*C

    float *xg1f, *xg1b, *xg2f, *xg2b, *h1f, *h1b, *hcat, *xgFf, *xgBf, *potB, *hst;
    cudaGetSymbolAddress((void**)&xg1f, g_xg1f);
    cudaGetSymbolAddress((void**)&xg1b, g_xg1b);
    cudaGetSymbolAddress((void**)&xg2f, g_xg2f);
    cudaGetSymbolAddress((void**)&xg2b, g_xg2b);
    cudaGetSymbolAddress((void**)&h1f,  g_h1f);
    cudaGetSymbolAddress((void**)&h1b,  g_h1b);
    cudaGetSymbolAddress((void**)&hcat, g_hcat);
    cudaGetSymbolAddress((void**)&xgFf, g_xgFf);
    cudaGetSymbolAddress((void**)&xgBf, g_xgBf);
    cudaGetSymbolAddress((void**)&potB, g_potB);
    cudaGetSymbolAddress((void**)&hst,  g_hstate);

    cudaFuncSetAttribute(scan_persist_kernel,
                         cudaFuncAttributeMaxDynamicSharedMemorySize, SCAN_SMEM);
    cudaFuncSetAttribute(final_lstm_kernel,
                         cudaFuncAttributeMaxDynamicSharedMemorySize, FIN_SMEM);
    cudaFuncSetAttribute(viterbi_kernel,
                         cudaFuncAttributeMaxDynamicSharedMemorySize, VIT_SMEM);

    dim3 g1(1024 / 128, BT / 128);  // (8, 256)
    gemm_bias_kernel<<<g1, 256>>>(x, Wi1f, b1f, xg1f, BT, 1024, 512);
    gemm_bias_kernel<<<g1, 256>>>(x, Wi1b, b1b, xg1b, BT, 1024, 512);

    dim3 gs(8, 8, 2);
    cudaMemsetAsync(hst, 0, sizeof(float) * 2 * 2 * HH * BB);
    reset_bar_kernel<<<1, 32>>>();
    scan_persist_kernel<<<gs, 256, SCAN_SMEM>>>(xg1f, xg1b, Wh1f, Wh1b,
                                                h1f, h1b, 256, 0, 0);

    gemm_bias_kernel<<<g1, 256>>>(h1f, Wi2f, b2f, xg2f, BT, 1024, 256);
    gemm_bias_kernel<<<g1, 256>>>(h1b, Wi2b, b2b, xg2b, BT, 1024, 256);

    cudaMemsetAsync(hst, 0, sizeof(float) * 2 * 2 * HH * BB);
    reset_bar_kernel<<<1, 32>>>();
    scan_persist_kernel<<<gs, 256, SCAN_SMEM>>>(xg2f, xg2b, Wh2f, Wh2b,
                                                hcat, hcat, 512, 0, 256);

    dim3 g2(384 / 128, BT / 128);   // (3, 256)
    gemm_bias_kernel<<<g2, 256>>>(hcat, Wif, bf, xgFf, BT, 384, 512);
    gemm_bias_kernel<<<g2, 256>>>(hcat, Wib, bb, xgBf, BT, 384, 512);

    dim3 gf(BB, 2);
    final_lstm_kernel<<<gf, 384, FIN_SMEM>>>(xgFf, xgBf, Whf, Whb, pot, potB);
    viterbi_kernel<<<BB, 128, VIT_SMEM>>>(pot, potB, trans, dec);
}

// round 10
// speedup vs baseline: 1.4052x; 1.0381x over previous
#include <cuda_runtime.h>
#include <math.h>

#define BB 128
#define TT 256
#define DD 512
#define HH 256
#define NC 96
#define BT (BB*TT)

// ---------------- scratch (static device globals; no runtime alloc) --------
__device__ float g_xg1f[(size_t)BT*1024];
__device__ float g_xg1b[(size_t)BT*1024];
__device__ float g_xg2f[(size_t)BT*1024];
__device__ float g_xg2b[(size_t)BT*1024];
__device__ float g_h1f[(size_t)BT*HH];
__device__ float g_h1b[(size_t)BT*HH];
__device__ float g_hcat[(size_t)BT*2*HH];
__device__ float g_xgFf[(size_t)BT*384];
__device__ float g_xgBf[(size_t)BT*384];
__device__ float g_potB[(size_t)BT*NC];
__device__ float g_hstate[2*2*HH*BB];     // [buf][dir][u][b]
// 16 group barrier counters (8 CTAs each), padded 256B apart
__device__ unsigned g_cnt[16*64];

// ---------------------------------------------------------------------------
// GEMM v2 (unchanged from R9): 128x128 tile, BK=16, f32x2, reg double-buffer.
// ---------------------------------------------------------------------------
__global__ __launch_bounds__(256, 2)
void gemm_bias_kernel(const float* __restrict__ A, const float* __restrict__ Bm,
                      const float* __restrict__ bias, float* __restrict__ C,
                      int M, int N, int K)
{
    __shared__ float As[16][132];
    __shared__ float Bs[16][128];

    const int tid = threadIdx.x;
    const int m0  = blockIdx.y * 128;
    const int n0  = blockIdx.x * 128;
    const int txn = tid & 15;
    const int tym = tid >> 4;

    const int arow = tid >> 2;
    const int akg  = (tid & 3) * 4;
    const int bkk = tid >> 5;
    const int bn  = (tid & 31) * 4;

    unsigned long long acc[4][8];
#pragma unroll
    for (int p = 0; p < 4; p++)
#pragma unroll
        for (int j = 0; j < 8; j++) acc[p][j] = 0ull;

    const int T = K / 16;
    float4 aR0, aR1, bR0, bR1;

    aR0 = *(const float4*)&A[(size_t)(m0 + arow) * K + akg];
    aR1 = *(const float4*)&A[(size_t)(m0 + 64 + arow) * K + akg];
    bR0 = *(const float4*)&Bm[(size_t)bkk * N + n0 + bn];
    bR1 = *(const float4*)&Bm[(size_t)(8 + bkk) * N + n0 + bn];
    {
        As[akg + 0][arow] = aR0.x; As[akg + 1][arow] = aR0.y;
        As[akg + 2][arow] = aR0.z; As[akg + 3][arow] = aR0.w;
        As[akg + 0][64 + arow] = aR1.x; As[akg + 1][64 + arow] = aR1.y;
        As[akg + 2][64 + arow] = aR1.z; As[akg + 3][64 + arow] = aR1.w;
        *(float4*)&Bs[bkk][bn] = bR0;
        *(float4*)&Bs[8 + bkk][bn] = bR1;
    }
    __syncthreads();

    for (int t = 0; t < T; t++) {
        if (t + 1 < T) {
            int k0 = (t + 1) * 16;
            aR0 = *(const float4*)&A[(size_t)(m0 + arow) * K + k0 + akg];
            aR1 = *(const float4*)&A[(size_t)(m0 + 64 + arow) * K + k0 + akg];
            bR0 = *(const float4*)&Bm[(size_t)(k0 + bkk) * N + n0 + bn];
            bR1 = *(const float4*)&Bm[(size_t)(k0 + 8 + bkk) * N + n0 + bn];
        }
#pragma unroll
        for (int kk = 0; kk < 16; kk++) {
            ulonglong2 aP0 = *(const ulonglong2*)&As[kk][tym * 8];
            ulonglong2 aP1 = *(const ulonglong2*)&As[kk][tym * 8 + 4];
            float4 b0 = *(const float4*)&Bs[kk][txn * 8];
            float4 b1 = *(const float4*)&Bs[kk][txn * 8 + 4];
            unsigned long long bd[8];
            asm("mov.b64 %0, {%1, %1};" : "=l"(bd[0]) : "f"(b0.x));
            asm("mov.b64 %0, {%1, %1};" : "=l"(bd[1]) : "f"(b0.y));
            asm("mov.b64 %0, {%1, %1};" : "=l"(bd[2]) : "f"(b0.z));
            asm("mov.b64 %0, {%1, %1};" : "=l"(bd[3]) : "f"(b0.w));
            asm("mov.b64 %0, {%1, %1};" : "=l"(bd[4]) : "f"(b1.x));
            asm("mov.b64 %0, {%1, %1};" : "=l"(bd[5]) : "f"(b1.y));
            asm("mov.b64 %0, {%1, %1};" : "=l"(bd[6]) : "f"(b1.z));
            asm("mov.b64 %0, {%1, %1};" : "=l"(bd[7]) : "f"(b1.w));
            unsigned long long ap[4] = {aP0.x, aP0.y, aP1.x, aP1.y};
#pragma unroll
            for (int p = 0; p < 4; p++)
#pragma unroll
                for (int j = 0; j < 8; j++)
                    asm("fma.rn.f32x2 %0, %1, %2, %0;"
                        : "+l"(acc[p][j]) : "l"(ap[p]), "l"(bd[j]));
        }
        __syncthreads();
        if (t + 1 < T) {
            As[akg + 0][arow] = aR0.x; As[akg + 1][arow] = aR0.y;
            As[akg + 2][arow] = aR0.z; As[akg + 3][arow] = aR0.w;
            As[akg + 0][64 + arow] = aR1.x; As[akg + 1][64 + arow] = aR1.y;
            As[akg + 2][64 + arow] = aR1.z; As[akg + 3][64 + arow] = aR1.w;
            *(float4*)&Bs[bkk][bn] = bR0;
            *(float4*)&Bs[8 + bkk][bn] = bR1;
            __syncthreads();
        }
    }

    float4 z0 = *(const float4*)&bias[n0 + txn * 8];
    float4 z1 = *(const float4*)&bias[n0 + txn * 8 + 4];
    float bz[8] = {z0.x, z0.y, z0.z, z0.w, z1.x, z1.y, z1.z, z1.w};
#pragma unroll
    for (int p = 0; p < 4; p++) {
        float lo[8], hi[8];
#pragma unroll
        for (int j = 0; j < 8; j++)
            asm("mov.b64 {%0, %1}, %2;" : "=f"(lo[j]), "=f"(hi[j]) : "l"(acc[p][j]));
        size_t r0 = (size_t)(m0 + tym * 8 + 2 * p) * N + n0 + txn * 8;
        size_t r1 = r0 + N;
        float4 v;
        v.x = lo[0] + bz[0]; v.y = lo[1] + bz[1]; v.z = lo[2] + bz[2]; v.w = lo[3] + bz[3];
        *(float4*)&C[r0] = v;
        v.x = lo[4] + bz[4]; v.y = lo[5] + bz[5]; v.z = lo[6] + bz[6]; v.w = lo[7] + bz[7];
        *(float4*)&C[r0 + 4] = v;
        v.x = hi[0] + bz[0]; v.y = hi[1] + bz[1]; v.z = hi[2] + bz[2]; v.w = hi[3] + bz[3];
        *(float4*)&C[r1] = v;
        v.x = hi[4] + bz[4]; v.y = hi[5] + bz[5]; v.z = hi[6] + bz[6]; v.w = hi[7] + bz[7];
        *(float4*)&C[r1 + 4] = v;
    }
}

// ---------------------------------------------------------------------------
__global__ void reset_bar_kernel()
{
    int i = threadIdx.x;
    if (i < 16) g_cnt[i * 64] = 0u;
}

// ---------------------------------------------------------------------------
// Persistent dual-direction LSTM scan v2.
// z-phase retile: 256 thr = 32 colgroups(4c) x 2 bgroups(8b) x 4 kbands(64k).
// Per k: 2 broadcast LDS.128 (h) + 1 LDS.128 (w) feed 16 f32x2 -> FMA-bound.
// Band partials (u64 b-pairs) in padded smem, reduced in the gate phase.
// Barrier: atom.add.release.gpu + acquire-poll (no separate fences).
// ---------------------------------------------------------------------------
#define ZROW 33  // u64 per column row: 8 bpairs x 4 bands + 1 pad
#define SCAN_SMEM (256*128*4 + 256*16*4 + 128*ZROW*8)

__global__ __launch_bounds__(256, 1)
void scan_persist_kernel(const float* __restrict__ xgF, const float* __restrict__ xgB,
                         const float* __restrict__ WhF, const float* __restrict__ WhB,
                         float* __restrict__ outF, float* __restrict__ outB,
                         int outStride, int offF, int offB)
{
    extern __shared__ float sm[];
    float* Ws = sm;                               // [256 k][128 c]
    float* hT = Ws + 256 * 128;                   // [256 k][16 b]
    unsigned long long* zP =
        (unsigned long long*)(hT + 256 * 16);     // [128 c][ZROW]

    const int tid = threadIdx.x;
    const int u0  = blockIdx.x * 32;
    const int b0  = blockIdx.y * 16;
    const int dir = blockIdx.z;
    const float* Wh = dir ? WhB : WhF;
    const float* xg = dir ? xgB : xgF;
    float* out = dir ? outB : outF;
    const int off = dir ? offB : offF;
    unsigned* cnt = &g_cnt[(dir * 8 + blockIdx.y) * 64];

    // stage Wh slice once: Ws[k][g*32+q] = Wh[k][g*256+u0+q]
#pragma unroll
    for (int i = 0; i < 32; i++) {
        int v = i * 256 + tid;
        int k = v >> 5, c4 = v & 31;
        int gate = c4 >> 3, q = c4 & 7;
        float4 w = *(const float4*)(Wh + (size_t)k * 1024 + gate * 256 + u0 + q * 4);
        *(float4*)(Ws + k * 128 + gate * 32 + q * 4) = w;
    }

    // z-phase mapping
    const int colg = tid & 31;          // 4 cols: c4..c4+3
    const int bgz  = (tid >> 5) & 1;    // 8 batches: bgz*8..+7
    const int band = tid >> 6;          // 64 k: band*64..+63
    const int c4   = colg * 4;

    // gate-phase mapping: unit pairs
    const int gq = tid & 15;            // unit pair: u0 + gq*2, +1
    const int gb = tid >> 4;            // batch 0..15
    const int bg = b0 + gb;
    float creg0 = 0.0f, creg1 = 0.0f;

#pragma unroll 1
    for (int s = 0; s < TT; s++) {
        const int t = dir ? (TT - 1 - s) : s;
        const float* hr = g_hstate + (size_t)(s & 1) * (2 * HH * BB) + dir * (HH * BB);
        float*       hw = g_hstate + (size_t)((s + 1) & 1) * (2 * HH * BB) + dir * (HH * BB);

        // stage h FIRST (critical path; don't queue behind xg DRAM loads)
#pragma unroll
        for (int i = 0; i < 4; i++) {
            int v = i * 256 + tid;
            int k = v >> 2, b4 = v & 3;
            float4 h = __ldcg((const float4*)(hr + k * 128 + b0 + b4 * 4));
            *(float4*)(hT + k * 16 + b4 * 4) = h;
        }

        // prefetch xg gate inputs (float2 per gate)
        const size_t xrow = ((size_t)bg * TT + t) * 1024;
        float2 xv[4];
#pragma unroll
        for (int g = 0; g < 4; g++)
            xv[g] = *(const float2*)(xg + xrow + g * 256 + u0 + gq * 2);

        __syncthreads();

        // z partial: 4 cols x 4 b-pairs over this thread's 64-k band
        unsigned long long acc[4][4];
#pragma unroll
        for (int j = 0; j < 4; j++)
#pragma unroll
            for (int p = 0; p < 4; p++) acc[j][p] = 0ull;

        const float* hb = hT + bgz * 8;
        const float* wb = Ws + c4;
        const int kb = band * 64;
#pragma unroll 4
        for (int kk = 0; kk < 64; kk++) {
            int k = kb + kk;
            ulonglong2 h01 = *(const ulonglong2*)(hb + k * 16);       // bpairs 0,1
            ulonglong2 h23 = *(const ulonglong2*)(hb + k * 16 + 4);   // bpairs 2,3
            float4 w4 = *(const float4*)(wb + k * 128);
            unsigned long long wd[4];
            asm("mov.b64 %0, {%1, %1};" : "=l"(wd[0]) : "f"(w4.x));
            asm("mov.b64 %0, {%1, %1};" : "=l"(wd[1]) : "f"(w4.y));
            asm("mov.b64 %0, {%1, %1};" : "=l"(wd[2]) : "f"(w4.z));
            asm("mov.b64 %0, {%1, %1};" : "=l"(wd[3]) : "f"(w4.w));
#pragma unroll
            for (int j = 0; j < 4; j++) {
                asm("fma.rn.f32x2 %0, %1, %2, %0;" : "+l"(acc[j][0]) : "l"(h01.x), "l"(wd[j]));
                asm("fma.rn.f32x2 %0, %1, %2, %0;" : "+l"(acc[j][1]) : "l"(h01.y), "l"(wd[j]));
                asm("fma.rn.f32x2 %0, %1, %2, %0;" : "+l"(acc[j][2]) : "l"(h23.x), "l"(wd[j]));
                asm("fma.rn.f32x2 %0, %1, %2, %0;" : "+l"(acc[j][3]) : "l"(h23.y), "l"(wd[j]));
            }
        }
        // store partials: zP[c][bp*4 + band], bp = bgz*4 + p
#pragma unroll
        for (int j = 0; j < 4; j++)
#pragma unroll
            for (int p = 0; p < 4; p++)
                zP[(c4 + j) * ZROW + (bgz * 4 + p) * 4 + band] = acc[j][p];
        __syncthreads();

        // gate phase: thread handles units u0+gq*2, +1 for batch gb
        {
            const unsigned* zw = (const unsigned*)zP;
            const int bp4 = (gb >> 1) * 4;     // bpair*4
            const int lohi = gb & 1;
            float zz[8];
#pragma unroll
            for (int g = 0; g < 4; g++) {
#pragma unroll
                for (int j = 0; j < 2; j++) {
                    int c = g * 32 + gq * 2 + j;
                    const unsigned* r = zw + 2 * (c * ZROW + bp4) + lohi;
                    float sum = __uint_as_float(r[0]) + __uint_as_float(r[2])
                              + __uint_as_float(r[4]) + __uint_as_float(r[6]);
                    zz[g * 2 + j] = sum;
                }
            }
            float hn2[2];
#pragma unroll
            for (int j = 0; j < 2; j++) {
                float zi = zz[0 + j] + (j ? xv[0].y : xv[0].x);
                float zf = zz[2 + j] + (j ? xv[1].y : xv[1].x);
                float zg = zz[4 + j] + (j ? xv[2].y : xv[2].x);
                float zo = zz[6 + j] + (j ? xv[3].y : xv[3].x);
                float iv = 1.f / (1.f + expf(-zi));
                float fv = 1.f / (1.f + expf(-zf));
                float ov = 1.f / (1.f + expf(-zo));
                float cold = j ? creg1 : creg0;
                float cn = fv * cold + iv * tanhf(zg);
                float hn = ov * tanhf(cn);
                if (j) creg1 = cn; else creg0 = cn;
                hn2[j] = hn;
                __stcg(hw + (size_t)(u0 + gq * 2 + j) * BB + bg, hn);
            }
            float2 o2; o2.x = hn2[0]; o2.y = hn2[1];
            *(float2*)(out + ((size_t)bg * TT + t) * outStride + off + u0 + gq * 2) = o2;
        }

        // group counting barrier: release-RMW arrive; acquire-poll same counter
        __syncthreads();
        if (tid == 0) {
            unsigned dummy;
            asm volatile("atom.add.release.gpu.global.u32 %0, [%1], 1;"
                         : "=r"(dummy) : "l"(cnt) : "memory");
            unsigned tgt = (unsigned)(s + 1) * 8u;
            unsigned f;
            do {
                asm volatile("ld.acquire.gpu.global.u32 %0, [%1];"
                             : "=r"(f) : "l"(cnt) : "memory");
            } while (f < tgt);
        }
        __syncthreads();
    }
}

// ---------------------------------------------------------------------------
// Final LSTMs (C=96, softmax activation), one CTA per (sample, direction).
// ---------------------------------------------------------------------------
__device__ __forceinline__ float blockReduce96(float v, bool isMax,
                                               volatile float* red, int tid)
{
#pragma unroll
    for (int o = 16; o > 0; o >>= 1) {
        float w = __shfl_down_sync(0xffffffffu, v, o);
        v = isMax ? fmaxf(v, w) : v + w;
    }
    if (tid < 96 && (tid & 31) == 0) red[tid >> 5] = v;
    __syncthreads();
    float r = isMax ? fmaxf(fmaxf(red[0], red[1]), red[2])
                    : red[0] + red[1] + red[2];
    __syncthreads();
    return r;
}

#define FIN_SMEM ((96*384 + 384 + 96 + 96 + 4) * 4)

__global__ __launch_bounds__(384)
void final_lstm_kernel(const float* __restrict__ xgF, const float* __restrict__ xgB,
                       const float* __restrict__ WhF, const float* __restrict__ WhB,
                       float* __restrict__ potF, float* __restrict__ potB)
{
    extern __shared__ float sm[];
    float* WhS = sm;
    float* zS  = WhS + 96 * 384;
    float* hS  = zS + 384;
    float* cS  = hS + 96;
    float* red = cS + 96;
    const int tid = threadIdx.x;
    const int b = blockIdx.x;
    const int dir = blockIdx.y;

    const float* Wh = dir ? WhB : WhF;
    const float* xg = dir ? xgB : xgF;
    float* pot = dir ? potB : potF;

    for (int i = tid; i < 96 * 384; i += 384) WhS[i] = Wh[i];
    if (tid < 96) { hS[tid] = 0.f; cS[tid] = 0.f; }
    __syncthreads();

    for (int s = 0; s < TT; s++) {
        int t = dir ? (TT - 1 - s) : s;
        float a = xg[((size_t)b * TT + t) * 384 + tid];
#pragma unroll 4
        for (int k = 0; k < 96; k++) a += hS[k] * WhS[k * 384 + tid];
        zS[tid] = a;
        __syncthreads();

        bool v = tid < 96;
        float gv = v ? zS[192 + tid] : -1e30f;
        float gmax = blockReduce96(gv, true, red, tid);
        float ge = v ? expf(gv - gmax) : 0.f;
        float gsum = blockReduce96(ge, false, red, tid);
        float cn = 0.f;
        if (v) {
            float iv = 1.f / (1.f + expf(-zS[tid]));
            float fv = 1.f / (1.f + expf(-zS[96 + tid]));
            cn = fv * cS[tid] + iv * (ge / gsum);
        }
        float cmax = blockReduce96(v ? cn : -1e30f, true, red, tid);
        float ce = v ? expf(cn - cmax) : 0.f;
        float csum = blockReduce96(ce, false, red, tid);
        if (v) {
            float ov = 1.f / (1.f + expf(-zS[288 + tid]));
            float hv = ov * (ce / csum);
            cS[tid] = cn;
            hS[tid] = hv;
            pot[((size_t)b * TT + t) * 96 + tid] = hv;
        }
        __syncthreads();
    }
}

// ---------------------------------------------------------------------------
// Viterbi: one CTA per sample. Fuses pot = pf + pb (writes summed pot to d_out).
// ---------------------------------------------------------------------------
#define VIT_SMEM (96*96*4 + 2*96*4 + 255*96 + 64)

__global__ __launch_bounds__(128)
void viterbi_kernel(float* __restrict__ potF, const float* __restrict__ potB,
                    const float* __restrict__ trans, float* __restrict__ dec)
{
    extern __shared__ float sm[];
    float* tS  = sm;
    float* al  = tS + 96 * 96;
    float* al2 = al + 96;
    unsigned char* bp = (unsigned char*)(al2 + 96);
    const int tid = threadIdx.x;
    const int b = blockIdx.x;

    for (int i = tid; i < 96 * 96; i += 128) tS[i] = trans[i];
    if (tid < 96) {
        size_t i0 = ((size_t)b * TT) * 96 + tid;
        float p0 = potF[i0] + potB[i0];
        potF[i0] = p0;
        al[tid] = p0;
    }
    __syncthreads();

    for (int t = 1; t < TT; t++) {
        if (tid < 96) {
            float best = -1e30f; int bi = 0;
#pragma unroll 4
            for (int i = 0; i < 96; i++) {
                float sc = al[i] + tS[i * 96 + tid];
                if (sc > best) { best = sc; bi = i; }
            }
            size_t idx = ((size_t)b * TT + t) * 96 + tid;
            float p = potF[idx] + potB[idx];
            potF[idx] = p;
            al2[tid] = best + p;
            bp[(t - 1) * 96 + tid] = (unsigned char)bi;
        }
        __syncthreads();
        if (tid < 96) al[tid] = al2[tid];
        __syncthreads();
    }
    if (tid == 0) {
        int bestj = 0; float bv = al[0];
        for (int j = 1; j < 96; j++) if (al[j] > bv) { bv = al[j]; bestj = j; }
        int tag = bestj;
        dec[(size_t)b * TT + TT - 1] = (float)tag;
        for (int t = TT - 2; t >= 0; t--) {
            tag = bp[t * 96 + tag];
            dec[(size_t)b * TT + t] = (float)tag;
        }
    }
}

// ---------------------------------------------------------------------------
extern "C" void kernel_launch(void* const* d_in, const int* in_sizes, int n_in,
                              void* d_out, int out_size)
{
    const float* x    = (const float*)d_in[0];
    const float* Wi1f = (const float*)d_in[1];
    const float* Wh1f = (const float*)d_in[2];
    const float* b1f  = (const float*)d_in[3];
    const float* Wi2f = (const float*)d_in[4];
    const float* Wh2f = (const float*)d_in[5];
    const float* b2f  = (const float*)d_in[6];
    const float* Wi1b = (const float*)d_in[7];
    const float* Wh1b = (const float*)d_in[8];
    const float* b1b  = (const float*)d_in[9];
    const float* Wi2b = (const float*)d_in[10];
    const float* Wh2b = (const float*)d_in[11];
    const float* b2b  = (const float*)d_in[12];
    const float* Wif  = (const float*)d_in[13];
    const float* Whf  = (const float*)d_in[14];
    const float* bf   = (const float*)d_in[15];
    const float* Wib  = (const float*)d_in[16];
    const float* Whb  = (const float*)d_in[17];
    const float* bb   = (const float*)d_in[18];
    const float* trans= (const float*)d_in[19];

    float* dec = (float*)d_out;
    float* pot = (float*)d_out + BT;

    float *xg1f, *xg1b, *xg2f, *xg2b, *h1f, *h1b, *hcat, *xgFf, *xgBf, *potB, *hst;
    cudaGetSymbolAddress((void**)&xg1f, g_xg1f);
    cudaGetSymbolAddress((void**)&xg1b, g_xg1b);
    cudaGetSymbolAddress((void**)&xg2f, g_xg2f);
    cudaGetSymbolAddress((void**)&xg2b, g_xg2b);
    cudaGetSymbolAddress((void**)&h1f,  g_h1f);
    cudaGetSymbolAddress((void**)&h1b,  g_h1b);
    cudaGetSymbolAddress((void**)&hcat, g_hcat);
    cudaGetSymbolAddress((void**)&xgFf, g_xgFf);
    cudaGetSymbolAddress((void**)&xgBf, g_xgBf);
    cudaGetSymbolAddress((void**)&potB, g_potB);
    cudaGetSymbolAddress((void**)&hst,  g_hstate);

    cudaFuncSetAttribute(scan_persist_kernel,
                         cudaFuncAttributeMaxDynamicSharedMemorySize, SCAN_SMEM);
    cudaFuncSetAttribute(final_lstm_kernel,
                         cudaFuncAttributeMaxDynamicSharedMemorySize, FIN_SMEM);
    cudaFuncSetAttribute(viterbi_kernel,
                         cudaFuncAttributeMaxDynamicSharedMemorySize, VIT_SMEM);

    dim3 g1(1024 / 128, BT / 128);  // (8, 256)
    gemm_bias_kernel<<<g1, 256>>>(x, Wi1f, b1f, xg1f, BT, 1024, 512);
    gemm_bias_kernel<<<g1, 256>>>(x, Wi1b, b1b, xg1b, BT, 1024, 512);

    dim3 gs(8, 8, 2);
    cudaMemsetAsync(hst, 0, sizeof(float) * 2 * 2 * HH * BB);
    reset_bar_kernel<<<1, 32>>>();
    scan_persist_kernel<<<gs, 256, SCAN_SMEM>>>(xg1f, xg1b, Wh1f, Wh1b,
                                                h1f, h1b, 256, 0, 0);

    gemm_bias_kernel<<<g1, 256>>>(h1f, Wi2f, b2f, xg2f, BT, 1024, 256);
    gemm_bias_kernel<<<g1, 256>>>(h1b, Wi2b, b2b, xg2b, BT, 1024, 256);

    cudaMemsetAsync(hst, 0, sizeof(float) * 2 * 2 * HH * BB);
    reset_bar_kernel<<<1, 32>>>();
    scan_persist_kernel<<<gs, 256, SCAN_SMEM>>>(xg2f, xg2b, Wh2f, Wh2b,
                                                hcat, hcat, 512, 0, 256);

    dim3 g2(384 / 128, BT / 128);   // (3, 256)
    gemm_bias_kernel<<<g2, 256>>>(hcat, Wif, bf, xgFf, BT, 384, 512);
    gemm_bias_kernel<<<g2, 256>>>(hcat, Wib, bb, xgBf, BT, 384, 512);

    dim3 gf(BB, 2);
    final_lstm_kernel<<<gf, 384, FIN_SMEM>>>(xgFf, xgBf, Whf, Whb, pot, potB);
    viterbi_kernel<<<BB, 128, VIT_SMEM>>>(pot, potB, trans, dec);
}